// round 1
// baseline (speedup 1.0000x reference)
#include <cuda_runtime.h>
#include <cstdint>
#include <cstdio>

// Problem constants
#define Bsz 8
#define Tn  1024
#define Vn  8192
#define Dn  1024
#define Hn  16
#define Ln  6
#define HDn 64
#define BT  (Bsz*Tn)      // 8192 rows
#define D3  (3*Dn)        // 3072

// ---------------------------------------------------------------------------
// Scratch (static __device__ arrays: no allocation at kernel_launch time)
// ---------------------------------------------------------------------------
__device__ float g_x[(size_t)BT * Dn];        // residual stream
__device__ float g_h[(size_t)BT * Dn];        // layernorm output
__device__ float g_qkv[(size_t)BT * D3];      // qkv projections
__device__ float g_logits_scratch[(size_t)BT * Vn]; // fallback if out is loss-only
__device__ int   g_tok[BT];
__device__ float g_nll[BT];

// ---------------------------------------------------------------------------
// 1. Recover token ids from dense one-hot (exactly one 1.0 per row)
// ---------------------------------------------------------------------------
__global__ void __launch_bounds__(256) tok_kernel(const float* __restrict__ idx,
                                                  int* __restrict__ tok) {
    const int row = blockIdx.x;
    const float* r = idx + (size_t)row * Vn;
    for (int v = threadIdx.x; v < Vn; v += 256) {
        if (r[v] > 0.5f) tok[row] = v;   // only one element qualifies: race-free
    }
}

// ---------------------------------------------------------------------------
// 2. Embedding gather: x[row, d] = W_emb[d, tok[row]]
// ---------------------------------------------------------------------------
__global__ void __launch_bounds__(256) embed_kernel(const float* __restrict__ W_emb,
                                                    const int* __restrict__ tok,
                                                    float* __restrict__ x) {
    const int row = blockIdx.x;
    const int t = tok[row];
    float* xr = x + (size_t)row * Dn;
    for (int d = threadIdx.x; d < Dn; d += 256)
        xr[d] = W_emb[(size_t)d * Vn + t];
}

// ---------------------------------------------------------------------------
// 3. Parameterless LayerNorm over last dim (D=1024), eps=1e-5
// ---------------------------------------------------------------------------
__global__ void __launch_bounds__(256) ln_kernel(const float* __restrict__ in,
                                                 float* __restrict__ out) {
    const int row = blockIdx.x;
    const float* r = in + (size_t)row * Dn;
    float s = 0.f, ss = 0.f;
    for (int d = threadIdx.x; d < Dn; d += 256) {
        float v = r[d];
        s += v; ss += v * v;
    }
    #pragma unroll
    for (int o = 16; o > 0; o >>= 1) {
        s  += __shfl_xor_sync(0xffffffffu, s,  o);
        ss += __shfl_xor_sync(0xffffffffu, ss, o);
    }
    __shared__ float sb[8], qb[8];
    const int w = threadIdx.x >> 5, lane = threadIdx.x & 31;
    if (lane == 0) { sb[w] = s; qb[w] = ss; }
    __syncthreads();
    float ts = 0.f, tq = 0.f;
    #pragma unroll
    for (int i = 0; i < 8; i++) { ts += sb[i]; tq += qb[i]; }
    const float mu   = ts * (1.0f / Dn);
    const float var  = tq * (1.0f / Dn) - mu * mu;
    const float rstd = rsqrtf(var + 1e-5f);
    float* o2 = out + (size_t)row * Dn;
    for (int d = threadIdx.x; d < Dn; d += 256)
        o2[d] = (r[d] - mu) * rstd;
}

// ---------------------------------------------------------------------------
// 4. SGEMM: C[M,N] = A[M,K] * B[N,K]^T  (both row-major; "TN" form)
//    128x128 tiles, BK=16, 256 threads, 8x8 microtile.
// ---------------------------------------------------------------------------
__global__ void __launch_bounds__(256) gemm_tn_kernel(
    const float* __restrict__ A, const float* __restrict__ Bm,
    float* __restrict__ C, int M, int N, int K) {
    __shared__ float As[16][128];
    __shared__ float Bs[16][128];
    const int tid = threadIdx.x;
    const int tx = tid & 15;
    const int ty = tid >> 4;
    const int bx = blockIdx.x, by = blockIdx.y;
    const float* Ab = A  + (size_t)by * 128 * K;
    const float* Bb = Bm + (size_t)bx * 128 * K;
    const int lr = tid >> 2;          // 0..63
    const int lc = (tid & 3) << 2;    // 0,4,8,12

    float acc[8][8];
    #pragma unroll
    for (int i = 0; i < 8; i++)
        #pragma unroll
        for (int j = 0; j < 8; j++) acc[i][j] = 0.f;

    for (int k0 = 0; k0 < K; k0 += 16) {
        float4 a0 = *(const float4*)(Ab + (size_t)lr        * K + k0 + lc);
        float4 a1 = *(const float4*)(Ab + (size_t)(lr + 64) * K + k0 + lc);
        float4 b0 = *(const float4*)(Bb + (size_t)lr        * K + k0 + lc);
        float4 b1 = *(const float4*)(Bb + (size_t)(lr + 64) * K + k0 + lc);
        __syncthreads();   // previous iteration finished reading smem
        As[lc + 0][lr] = a0.x; As[lc + 1][lr] = a0.y; As[lc + 2][lr] = a0.z; As[lc + 3][lr] = a0.w;
        As[lc + 0][lr + 64] = a1.x; As[lc + 1][lr + 64] = a1.y; As[lc + 2][lr + 64] = a1.z; As[lc + 3][lr + 64] = a1.w;
        Bs[lc + 0][lr] = b0.x; Bs[lc + 1][lr] = b0.y; Bs[lc + 2][lr] = b0.z; Bs[lc + 3][lr] = b0.w;
        Bs[lc + 0][lr + 64] = b1.x; Bs[lc + 1][lr + 64] = b1.y; Bs[lc + 2][lr + 64] = b1.z; Bs[lc + 3][lr + 64] = b1.w;
        __syncthreads();
        #pragma unroll
        for (int k = 0; k < 16; k++) {
            float ar[8], br[8];
            #pragma unroll
            for (int i = 0; i < 8; i++) ar[i] = As[k][ty * 8 + i];
            #pragma unroll
            for (int j = 0; j < 8; j++) br[j] = Bs[k][tx * 8 + j];
            #pragma unroll
            for (int i = 0; i < 8; i++)
                #pragma unroll
                for (int j = 0; j < 8; j++) acc[i][j] += ar[i] * br[j];
        }
    }
    #pragma unroll
    for (int i = 0; i < 8; i++) {
        float* cp = C + (size_t)(by * 128 + ty * 8 + i) * N + bx * 128 + tx * 8;
        *(float4*)(cp)     = make_float4(acc[i][0], acc[i][1], acc[i][2], acc[i][3]);
        *(float4*)(cp + 4) = make_float4(acc[i][4], acc[i][5], acc[i][6], acc[i][7]);
    }
}

// ---------------------------------------------------------------------------
// 5. Causal flash attention, fp32.
//    Block = (qtile=64 queries, head, batch). Threads=256.
//    Smem: Q[64][64] + K[64][64] (reused for P^T) + V[64][64] = exactly 48 KB.
//    Each thread owns one query row q=tid/4 and 16 cols/dims cb=(tid%4)*16.
//    Output accumulated directly into the residual stream: x += o.
// ---------------------------------------------------------------------------
__global__ void __launch_bounds__(256) attn_kernel(const float* __restrict__ qkv,
                                                   float* __restrict__ x) {
    __shared__ float Qs[64 * 64];
    __shared__ float Ks[64 * 64];   // reused as P^T after scores are consumed
    __shared__ float Vs[64 * 64];

    const int qt = blockIdx.x;     // 0..15
    const int h  = blockIdx.y;     // 0..15
    const int b  = blockIdx.z;     // 0..7
    const int tid = threadIdx.x;
    const int q  = tid >> 2;            // 0..63 query row within tile
    const int cb = (tid & 3) << 4;      // 0,16,32,48 column/dim base
    const int qpos = qt * 64 + q;

    const size_t rowbase = (size_t)b * Tn * D3;
    const int hoff = h * HDn;

    // load Q tile (coalesced over head dim)
    for (int i = tid; i < 4096; i += 256) {
        const int r = i >> 6, c = i & 63;
        Qs[i] = qkv[rowbase + (size_t)(qt * 64 + r) * D3 + hoff + c];
    }

    float m = -1e30f, l = 0.f;
    float acc[16];
    #pragma unroll
    for (int i = 0; i < 16; i++) acc[i] = 0.f;

    for (int jt = 0; jt <= qt; jt++) {
        __syncthreads();   // prior tile fully consumed; Q writes visible (iter 0)
        for (int i = tid; i < 4096; i += 256) {
            const int r = i >> 6, c = i & 63;
            const size_t base = rowbase + (size_t)(jt * 64 + r) * D3 + hoff + c;
            Ks[i] = qkv[base + Dn];
            Vs[i] = qkv[base + 2 * Dn];
        }
        __syncthreads();

        // scores s[i] = <Q[q,:], K[cb+i,:]>
        float s[16];
        #pragma unroll
        for (int i = 0; i < 16; i++) s[i] = 0.f;
        #pragma unroll
        for (int dc = 0; dc < 64; dc += 16) {
            const float4* qr = (const float4*)&Qs[q * 64 + dc];
            float4 q0 = qr[0], q1 = qr[1], q2 = qr[2], q3 = qr[3];
            #pragma unroll
            for (int i = 0; i < 16; i++) {
                const float4* kr = (const float4*)&Ks[(cb + i) * 64 + dc];
                float4 k0 = kr[0], k1 = kr[1], k2 = kr[2], k3 = kr[3];
                s[i] += q0.x * k0.x + q0.y * k0.y + q0.z * k0.z + q0.w * k0.w
                      + q1.x * k1.x + q1.y * k1.y + q1.z * k1.z + q1.w * k1.w
                      + q2.x * k2.x + q2.y * k2.y + q2.z * k2.z + q2.w * k2.w
                      + q3.x * k3.x + q3.y * k3.y + q3.z * k3.z + q3.w * k3.w;
            }
        }
        // scale + causal mask
        const int kb = jt * 64 + cb;
        #pragma unroll
        for (int i = 0; i < 16; i++) {
            s[i] *= 0.125f;                       // 1/sqrt(64)
            if (kb + i > qpos) s[i] = -1e30f;
        }
        // online softmax (4-thread group owns one query row; consecutive lanes)
        float tm = s[0];
        #pragma unroll
        for (int i = 1; i < 16; i++) tm = fmaxf(tm, s[i]);
        tm = fmaxf(tm, __shfl_xor_sync(0xffffffffu, tm, 1));
        tm = fmaxf(tm, __shfl_xor_sync(0xffffffffu, tm, 2));
        const float nm = fmaxf(m, tm);
        const float corr = __expf(m - nm);
        float tsum = 0.f;
        #pragma unroll
        for (int i = 0; i < 16; i++) { s[i] = __expf(s[i] - nm); tsum += s[i]; }
        tsum += __shfl_xor_sync(0xffffffffu, tsum, 1);
        tsum += __shfl_xor_sync(0xffffffffu, tsum, 2);
        l = l * corr + tsum;
        m = nm;
        #pragma unroll
        for (int i = 0; i < 16; i++) acc[i] *= corr;

        __syncthreads();   // all threads done reading Ks
        // store P transposed into Ks memory: Pt[c][q]
        #pragma unroll
        for (int i = 0; i < 16; i++) Ks[(cb + i) * 64 + q] = s[i];
        __syncthreads();

        // acc[j] += sum_c P[q][c] * V[c][cb+j]
        #pragma unroll 4
        for (int c = 0; c < 64; c++) {
            const float pv = Ks[c * 64 + q];   // Pt[c][q] — conflict-free
            const float4* vr = (const float4*)&Vs[c * 64 + cb];
            float4 v0 = vr[0], v1 = vr[1], v2 = vr[2], v3 = vr[3];
            acc[0]  += pv * v0.x; acc[1]  += pv * v0.y; acc[2]  += pv * v0.z; acc[3]  += pv * v0.w;
            acc[4]  += pv * v1.x; acc[5]  += pv * v1.y; acc[6]  += pv * v1.z; acc[7]  += pv * v1.w;
            acc[8]  += pv * v2.x; acc[9]  += pv * v2.y; acc[10] += pv * v2.z; acc[11] += pv * v2.w;
            acc[12] += pv * v3.x; acc[13] += pv * v3.y; acc[14] += pv * v3.z; acc[15] += pv * v3.w;
        }
    }

    // residual add: x[b, qpos, h*64 + cb + j] += acc[j] / l   (disjoint ownership)
    const float inv = 1.0f / l;
    float* xr = &x[((size_t)b * Tn + qpos) * Dn + hoff + cb];
    #pragma unroll
    for (int i = 0; i < 16; i++) xr[i] += acc[i] * inv;
}

// ---------------------------------------------------------------------------
// 6. Per-row NLL: nll[row] = logsumexp(logits[row,:]) - logits[row, target]
// ---------------------------------------------------------------------------
__global__ void __launch_bounds__(256) nll_kernel(const float* __restrict__ logits,
                                                  const int* __restrict__ targets,
                                                  float* __restrict__ nll) {
    const int row = blockIdx.x;
    const float* r = logits + (size_t)row * Vn;
    float mx = -3.0e38f;
    for (int v = threadIdx.x; v < Vn; v += 256) mx = fmaxf(mx, r[v]);
    #pragma unroll
    for (int o = 16; o > 0; o >>= 1) mx = fmaxf(mx, __shfl_xor_sync(0xffffffffu, mx, o));
    __shared__ float mb[8];
    __shared__ float sbuf[8];
    const int w = threadIdx.x >> 5, lane = threadIdx.x & 31;
    if (lane == 0) mb[w] = mx;
    __syncthreads();
    float gm = mb[0];
    #pragma unroll
    for (int i = 1; i < 8; i++) gm = fmaxf(gm, mb[i]);

    float se = 0.f;
    for (int v = threadIdx.x; v < Vn; v += 256) se += __expf(r[v] - gm);
    #pragma unroll
    for (int o = 16; o > 0; o >>= 1) se += __shfl_xor_sync(0xffffffffu, se, o);
    if (lane == 0) sbuf[w] = se;
    __syncthreads();
    if (threadIdx.x == 0) {
        float tot = 0.f;
        #pragma unroll
        for (int i = 0; i < 8; i++) tot += sbuf[i];
        nll[row] = gm + logf(tot) - r[targets[row]];
    }
}

// ---------------------------------------------------------------------------
// 7. Deterministic mean over 8192 row NLLs
// ---------------------------------------------------------------------------
__global__ void __launch_bounds__(256) loss_kernel(const float* __restrict__ nll,
                                                   float* __restrict__ out) {
    float s = 0.f;
    for (int i = threadIdx.x; i < BT; i += 256) s += nll[i];
    #pragma unroll
    for (int o = 16; o > 0; o >>= 1) s += __shfl_xor_sync(0xffffffffu, s, o);
    __shared__ float sb[8];
    const int w = threadIdx.x >> 5, lane = threadIdx.x & 31;
    if (lane == 0) sb[w] = s;
    __syncthreads();
    if (threadIdx.x == 0) {
        float tot = 0.f;
        #pragma unroll
        for (int i = 0; i < 8; i++) tot += sb[i];
        out[0] = tot * (1.0f / BT);
    }
}

// ---------------------------------------------------------------------------
// Host entry
// ---------------------------------------------------------------------------
extern "C" void kernel_launch(void* const* d_in, const int* in_sizes, int n_in,
                              void* d_out, int out_size) {
    (void)in_sizes; (void)n_in;
    const float* idx     = (const float*)d_in[0];   // [B,T,V] one-hot f32
    const int*   targets = (const int*)d_in[1];     // [B,T] int32
    const float* W_emb   = (const float*)d_in[2];   // [D,V]
    const float* W_attn  = (const float*)d_in[3];   // [L,3D,D]
    const float* W_out   = (const float*)d_in[4];   // [V,D]
    float* out = (float*)d_out;

    float *x, *h, *qkv, *nll, *lscr;
    int* tok;
    cudaGetSymbolAddress((void**)&x,    g_x);
    cudaGetSymbolAddress((void**)&h,    g_h);
    cudaGetSymbolAddress((void**)&qkv,  g_qkv);
    cudaGetSymbolAddress((void**)&nll,  g_nll);
    cudaGetSymbolAddress((void**)&lscr, g_logits_scratch);
    cudaGetSymbolAddress((void**)&tok,  g_tok);

    const size_t BTV = (size_t)BT * Vn;
    float* logits = ((size_t)out_size >= BTV) ? out : lscr;
    float* lossp  = ((size_t)out_size > BTV) ? (out + BTV)
                  : ((out_size == 1) ? out : nullptr);

    tok_kernel<<<BT, 256>>>(idx, tok);
    embed_kernel<<<BT, 256>>>(W_emb, tok, x);

    for (int l = 0; l < Ln; l++) {
        ln_kernel<<<BT, 256>>>(x, h);
        gemm_tn_kernel<<<dim3(D3 / 128, BT / 128), 256>>>(
            h, W_attn + (size_t)l * D3 * Dn, qkv, BT, D3, Dn);
        attn_kernel<<<dim3(Tn / 64, Hn, Bsz), 256>>>(qkv, x);
    }

    ln_kernel<<<BT, 256>>>(x, h);
    gemm_tn_kernel<<<dim3(Vn / 128, BT / 128), 256>>>(h, W_out, logits, BT, Vn, Dn);

    if (lossp) {
        nll_kernel<<<BT, 256>>>(logits, targets, nll);
        loss_kernel<<<1, 256>>>(nll, lossp);
    }
}

// round 2
// speedup vs baseline: 1.3031x; 1.3031x over previous
#include <cuda_runtime.h>
#include <cstdint>
#include <cstdio>

// Problem constants
#define Bsz 8
#define Tn  1024
#define Vn  8192
#define Dn  1024
#define Hn  16
#define Ln  6
#define HDn 64
#define BT  (Bsz*Tn)      // 8192 rows
#define D3  (3*Dn)        // 3072

// ---------------------------------------------------------------------------
// Scratch (static __device__ arrays: no allocation at kernel_launch time)
// ---------------------------------------------------------------------------
__device__ float g_x[(size_t)BT * Dn];        // residual stream
__device__ float g_h[(size_t)BT * Dn];        // layernorm output
__device__ float g_qkv[(size_t)BT * D3];      // qkv projections
__device__ float g_logits_scratch[(size_t)BT * Vn]; // fallback if out is loss-only
__device__ int   g_tok[BT];
__device__ float g_nll[BT];

// ---------------------------------------------------------------------------
// 1. Recover token ids from dense one-hot (exactly one 1.0 per row)
// ---------------------------------------------------------------------------
__global__ void __launch_bounds__(256) tok_kernel(const float* __restrict__ idx,
                                                  int* __restrict__ tok) {
    const int row = blockIdx.x;
    const float* r = idx + (size_t)row * Vn;
    for (int v = threadIdx.x; v < Vn; v += 256) {
        if (r[v] > 0.5f) tok[row] = v;   // only one element qualifies: race-free
    }
}

// ---------------------------------------------------------------------------
// 2. Embedding gather: x[row, d] = W_emb[d, tok[row]]
// ---------------------------------------------------------------------------
__global__ void __launch_bounds__(256) embed_kernel(const float* __restrict__ W_emb,
                                                    const int* __restrict__ tok,
                                                    float* __restrict__ x) {
    const int row = blockIdx.x;
    const int t = tok[row];
    float* xr = x + (size_t)row * Dn;
    for (int d = threadIdx.x; d < Dn; d += 256)
        xr[d] = W_emb[(size_t)d * Vn + t];
}

// ---------------------------------------------------------------------------
// 3. Parameterless LayerNorm over last dim (D=1024), eps=1e-5
// ---------------------------------------------------------------------------
__global__ void __launch_bounds__(256) ln_kernel(const float* __restrict__ in,
                                                 float* __restrict__ out) {
    const int row = blockIdx.x;
    const float* r = in + (size_t)row * Dn;
    float s = 0.f, ss = 0.f;
    for (int d = threadIdx.x; d < Dn; d += 256) {
        float v = r[d];
        s += v; ss += v * v;
    }
    #pragma unroll
    for (int o = 16; o > 0; o >>= 1) {
        s  += __shfl_xor_sync(0xffffffffu, s,  o);
        ss += __shfl_xor_sync(0xffffffffu, ss, o);
    }
    __shared__ float sb[8], qb[8];
    const int w = threadIdx.x >> 5, lane = threadIdx.x & 31;
    if (lane == 0) { sb[w] = s; qb[w] = ss; }
    __syncthreads();
    float ts = 0.f, tq = 0.f;
    #pragma unroll
    for (int i = 0; i < 8; i++) { ts += sb[i]; tq += qb[i]; }
    const float mu   = ts * (1.0f / Dn);
    const float var  = tq * (1.0f / Dn) - mu * mu;
    const float rstd = rsqrtf(var + 1e-5f);
    float* o2 = out + (size_t)row * Dn;
    for (int d = threadIdx.x; d < Dn; d += 256)
        o2[d] = (r[d] - mu) * rstd;
}

// ---------------------------------------------------------------------------
// tf32 helpers
// ---------------------------------------------------------------------------
__device__ __forceinline__ float f2tf32(float x) {
    uint32_t u;
    asm("cvt.rna.tf32.f32 %0, %1;" : "=r"(u) : "f"(x));
    return __uint_as_float(u);
}

__device__ __forceinline__ void mma_tf32(float* c, const uint32_t* a, const uint32_t* b) {
    asm volatile(
        "mma.sync.aligned.m16n8k8.row.col.f32.tf32.tf32.f32 "
        "{%0,%1,%2,%3}, {%4,%5,%6,%7}, {%8,%9}, {%0,%1,%2,%3};"
        : "+f"(c[0]), "+f"(c[1]), "+f"(c[2]), "+f"(c[3])
        : "r"(a[0]), "r"(a[1]), "r"(a[2]), "r"(a[3]),
          "r"(b[0]), "r"(b[1]));
}

// ---------------------------------------------------------------------------
// 4. tf32 tensor-core GEMM: C[M,N] = A[M,K] * B[N,K]^T (both row-major).
//    Block tile 128x128, BK=32, 256 threads = 8 warps (2x4).
//    Warp tile 64x32 = 4x4 m16n8k8 atoms. Smem stride 36 makes fragment
//    LDS bank index = (4*row + k) % 32 — lane-distinct, conflict-free.
//    Requires: M%128==0, N%128==0, K%32==0 (true for all shapes here).
// ---------------------------------------------------------------------------
__global__ void __launch_bounds__(256) gemm_tf32_kernel(
    const float* __restrict__ A, const float* __restrict__ Bm,
    float* __restrict__ C, int M, int N, int K) {
    __shared__ float As[128][36];
    __shared__ float Bs[128][36];

    const int tid  = threadIdx.x;
    const int warp = tid >> 5, lane = tid & 31;
    const int wm = (warp >> 2) * 64;     // warp row offset within block
    const int wn = (warp & 3) * 32;      // warp col offset within block
    const int bx = blockIdx.x, by = blockIdx.y;
    const float* Ab = A  + (size_t)by * 128 * K;
    const float* Bb = Bm + (size_t)bx * 128 * K;

    const int frow = lane >> 2;          // fragment row within m16 / n8 tile
    const int fcol = lane & 3;           // fragment k within k8

    float acc[4][4][4];
    #pragma unroll
    for (int i = 0; i < 4; i++)
        #pragma unroll
        for (int j = 0; j < 4; j++)
            #pragma unroll
            for (int v = 0; v < 4; v++) acc[i][j][v] = 0.f;

    // staging registers: 4 float4 of A, 4 float4 of B per iter
    float4 ra[4], rb[4];
    // float4 id = tid + i*256; row = id>>3, col = (id&7)*4
    #pragma unroll
    for (int i = 0; i < 4; i++) {
        const int id = tid + i * 256;
        const int r = id >> 3, c = (id & 7) << 2;
        ra[i] = *(const float4*)(Ab + (size_t)r * K + c);
        rb[i] = *(const float4*)(Bb + (size_t)r * K + c);
    }

    for (int k0 = 0; k0 < K; k0 += 32) {
        __syncthreads();   // previous iteration done reading smem
        #pragma unroll
        for (int i = 0; i < 4; i++) {
            const int id = tid + i * 256;
            const int r = id >> 3, c = (id & 7) << 2;
            As[r][c + 0] = f2tf32(ra[i].x); As[r][c + 1] = f2tf32(ra[i].y);
            As[r][c + 2] = f2tf32(ra[i].z); As[r][c + 3] = f2tf32(ra[i].w);
            Bs[r][c + 0] = f2tf32(rb[i].x); Bs[r][c + 1] = f2tf32(rb[i].y);
            Bs[r][c + 2] = f2tf32(rb[i].z); Bs[r][c + 3] = f2tf32(rb[i].w);
        }
        __syncthreads();

        // prefetch next global tile while computing this one
        if (k0 + 32 < K) {
            #pragma unroll
            for (int i = 0; i < 4; i++) {
                const int id = tid + i * 256;
                const int r = id >> 3, c = (id & 7) << 2;
                ra[i] = *(const float4*)(Ab + (size_t)r * K + k0 + 32 + c);
                rb[i] = *(const float4*)(Bb + (size_t)r * K + k0 + 32 + c);
            }
        }

        #pragma unroll
        for (int kk = 0; kk < 32; kk += 8) {
            uint32_t af[4][4], bf[4][2];
            #pragma unroll
            for (int mi = 0; mi < 4; mi++) {
                const int mr = wm + mi * 16 + frow;
                af[mi][0] = __float_as_uint(As[mr    ][kk + fcol    ]);
                af[mi][1] = __float_as_uint(As[mr + 8][kk + fcol    ]);
                af[mi][2] = __float_as_uint(As[mr    ][kk + fcol + 4]);
                af[mi][3] = __float_as_uint(As[mr + 8][kk + fcol + 4]);
            }
            #pragma unroll
            for (int nj = 0; nj < 4; nj++) {
                const int nr = wn + nj * 8 + frow;
                bf[nj][0] = __float_as_uint(Bs[nr][kk + fcol    ]);
                bf[nj][1] = __float_as_uint(Bs[nr][kk + fcol + 4]);
            }
            #pragma unroll
            for (int mi = 0; mi < 4; mi++)
                #pragma unroll
                for (int nj = 0; nj < 4; nj++)
                    mma_tf32(acc[mi][nj], af[mi], bf[nj]);
        }
    }

    // epilogue: c0,c1 at (row, 2*fcol), c2,c3 at (row+8, 2*fcol)
    #pragma unroll
    for (int mi = 0; mi < 4; mi++) {
        #pragma unroll
        for (int nj = 0; nj < 4; nj++) {
            const int row = by * 128 + wm + mi * 16 + frow;
            const int col = bx * 128 + wn + nj * 8 + fcol * 2;
            *(float2*)(C + (size_t)row * N + col) =
                make_float2(acc[mi][nj][0], acc[mi][nj][1]);
            *(float2*)(C + (size_t)(row + 8) * N + col) =
                make_float2(acc[mi][nj][2], acc[mi][nj][3]);
        }
    }
}

// ---------------------------------------------------------------------------
// 5. Causal flash attention, fp32 (smem-crossbar bound, ~1-3ms total; fine).
// ---------------------------------------------------------------------------
__global__ void __launch_bounds__(256) attn_kernel(const float* __restrict__ qkv,
                                                   float* __restrict__ x) {
    __shared__ float Qs[64 * 64];
    __shared__ float Ks[64 * 64];   // reused as P^T after scores are consumed
    __shared__ float Vs[64 * 64];

    const int qt = blockIdx.x;     // 0..15
    const int h  = blockIdx.y;     // 0..15
    const int b  = blockIdx.z;     // 0..7
    const int tid = threadIdx.x;
    const int q  = tid >> 2;            // 0..63 query row within tile
    const int cb = (tid & 3) << 4;      // 0,16,32,48 column/dim base
    const int qpos = qt * 64 + q;

    const size_t rowbase = (size_t)b * Tn * D3;
    const int hoff = h * HDn;

    for (int i = tid; i < 4096; i += 256) {
        const int r = i >> 6, c = i & 63;
        Qs[i] = qkv[rowbase + (size_t)(qt * 64 + r) * D3 + hoff + c];
    }

    float m = -1e30f, l = 0.f;
    float acc[16];
    #pragma unroll
    for (int i = 0; i < 16; i++) acc[i] = 0.f;

    for (int jt = 0; jt <= qt; jt++) {
        __syncthreads();
        for (int i = tid; i < 4096; i += 256) {
            const int r = i >> 6, c = i & 63;
            const size_t base = rowbase + (size_t)(jt * 64 + r) * D3 + hoff + c;
            Ks[i] = qkv[base + Dn];
            Vs[i] = qkv[base + 2 * Dn];
        }
        __syncthreads();

        float s[16];
        #pragma unroll
        for (int i = 0; i < 16; i++) s[i] = 0.f;
        #pragma unroll
        for (int dc = 0; dc < 64; dc += 16) {
            const float4* qr = (const float4*)&Qs[q * 64 + dc];
            float4 q0 = qr[0], q1 = qr[1], q2 = qr[2], q3 = qr[3];
            #pragma unroll
            for (int i = 0; i < 16; i++) {
                const float4* kr = (const float4*)&Ks[(cb + i) * 64 + dc];
                float4 k0 = kr[0], k1 = kr[1], k2 = kr[2], k3 = kr[3];
                s[i] += q0.x * k0.x + q0.y * k0.y + q0.z * k0.z + q0.w * k0.w
                      + q1.x * k1.x + q1.y * k1.y + q1.z * k1.z + q1.w * k1.w
                      + q2.x * k2.x + q2.y * k2.y + q2.z * k2.z + q2.w * k2.w
                      + q3.x * k3.x + q3.y * k3.y + q3.z * k3.z + q3.w * k3.w;
            }
        }
        const int kb = jt * 64 + cb;
        #pragma unroll
        for (int i = 0; i < 16; i++) {
            s[i] *= 0.125f;
            if (kb + i > qpos) s[i] = -1e30f;
        }
        float tm = s[0];
        #pragma unroll
        for (int i = 1; i < 16; i++) tm = fmaxf(tm, s[i]);
        tm = fmaxf(tm, __shfl_xor_sync(0xffffffffu, tm, 1));
        tm = fmaxf(tm, __shfl_xor_sync(0xffffffffu, tm, 2));
        const float nm = fmaxf(m, tm);
        const float corr = __expf(m - nm);
        float tsum = 0.f;
        #pragma unroll
        for (int i = 0; i < 16; i++) { s[i] = __expf(s[i] - nm); tsum += s[i]; }
        tsum += __shfl_xor_sync(0xffffffffu, tsum, 1);
        tsum += __shfl_xor_sync(0xffffffffu, tsum, 2);
        l = l * corr + tsum;
        m = nm;
        #pragma unroll
        for (int i = 0; i < 16; i++) acc[i] *= corr;

        __syncthreads();
        #pragma unroll
        for (int i = 0; i < 16; i++) Ks[(cb + i) * 64 + q] = s[i];
        __syncthreads();

        #pragma unroll 4
        for (int c = 0; c < 64; c++) {
            const float pv = Ks[c * 64 + q];
            const float4* vr = (const float4*)&Vs[c * 64 + cb];
            float4 v0 = vr[0], v1 = vr[1], v2 = vr[2], v3 = vr[3];
            acc[0]  += pv * v0.x; acc[1]  += pv * v0.y; acc[2]  += pv * v0.z; acc[3]  += pv * v0.w;
            acc[4]  += pv * v1.x; acc[5]  += pv * v1.y; acc[6]  += pv * v1.z; acc[7]  += pv * v1.w;
            acc[8]  += pv * v2.x; acc[9]  += pv * v2.y; acc[10] += pv * v2.z; acc[11] += pv * v2.w;
            acc[12] += pv * v3.x; acc[13] += pv * v3.y; acc[14] += pv * v3.z; acc[15] += pv * v3.w;
        }
    }

    const float inv = 1.0f / l;
    float* xr = &x[((size_t)b * Tn + qpos) * Dn + hoff + cb];
    #pragma unroll
    for (int i = 0; i < 16; i++) xr[i] += acc[i] * inv;
}

// ---------------------------------------------------------------------------
// 6. Per-row NLL: nll[row] = logsumexp(logits[row,:]) - logits[row, target]
// ---------------------------------------------------------------------------
__global__ void __launch_bounds__(256) nll_kernel(const float* __restrict__ logits,
                                                  const int* __restrict__ targets,
                                                  float* __restrict__ nll) {
    const int row = blockIdx.x;
    const float* r = logits + (size_t)row * Vn;
    float mx = -3.0e38f;
    for (int v = threadIdx.x; v < Vn; v += 256) mx = fmaxf(mx, r[v]);
    #pragma unroll
    for (int o = 16; o > 0; o >>= 1) mx = fmaxf(mx, __shfl_xor_sync(0xffffffffu, mx, o));
    __shared__ float mb[8];
    __shared__ float sbuf[8];
    const int w = threadIdx.x >> 5, lane = threadIdx.x & 31;
    if (lane == 0) mb[w] = mx;
    __syncthreads();
    float gm = mb[0];
    #pragma unroll
    for (int i = 1; i < 8; i++) gm = fmaxf(gm, mb[i]);

    float se = 0.f;
    for (int v = threadIdx.x; v < Vn; v += 256) se += __expf(r[v] - gm);
    #pragma unroll
    for (int o = 16; o > 0; o >>= 1) se += __shfl_xor_sync(0xffffffffu, se, o);
    if (lane == 0) sbuf[w] = se;
    __syncthreads();
    if (threadIdx.x == 0) {
        float tot = 0.f;
        #pragma unroll
        for (int i = 0; i < 8; i++) tot += sbuf[i];
        nll[row] = gm + logf(tot) - r[targets[row]];
    }
}

// ---------------------------------------------------------------------------
// 7. Deterministic mean over 8192 row NLLs
// ---------------------------------------------------------------------------
__global__ void __launch_bounds__(256) loss_kernel(const float* __restrict__ nll,
                                                   float* __restrict__ out) {
    float s = 0.f;
    for (int i = threadIdx.x; i < BT; i += 256) s += nll[i];
    #pragma unroll
    for (int o = 16; o > 0; o >>= 1) s += __shfl_xor_sync(0xffffffffu, s, o);
    __shared__ float sb[8];
    const int w = threadIdx.x >> 5, lane = threadIdx.x & 31;
    if (lane == 0) sb[w] = s;
    __syncthreads();
    if (threadIdx.x == 0) {
        float tot = 0.f;
        #pragma unroll
        for (int i = 0; i < 8; i++) tot += sb[i];
        out[0] = tot * (1.0f / BT);
    }
}

// ---------------------------------------------------------------------------
// Host entry
// ---------------------------------------------------------------------------
extern "C" void kernel_launch(void* const* d_in, const int* in_sizes, int n_in,
                              void* d_out, int out_size) {
    (void)in_sizes; (void)n_in;
    const float* idx     = (const float*)d_in[0];   // [B,T,V] one-hot f32
    const int*   targets = (const int*)d_in[1];     // [B,T] int32
    const float* W_emb   = (const float*)d_in[2];   // [D,V]
    const float* W_attn  = (const float*)d_in[3];   // [L,3D,D]
    const float* W_out   = (const float*)d_in[4];   // [V,D]
    float* out = (float*)d_out;

    float *x, *h, *qkv, *nll, *lscr;
    int* tok;
    cudaGetSymbolAddress((void**)&x,    g_x);
    cudaGetSymbolAddress((void**)&h,    g_h);
    cudaGetSymbolAddress((void**)&qkv,  g_qkv);
    cudaGetSymbolAddress((void**)&nll,  g_nll);
    cudaGetSymbolAddress((void**)&lscr, g_logits_scratch);
    cudaGetSymbolAddress((void**)&tok,  g_tok);

    const size_t BTV = (size_t)BT * Vn;
    float* logits = ((size_t)out_size >= BTV) ? out : lscr;
    float* lossp  = ((size_t)out_size > BTV) ? (out + BTV)
                  : ((out_size == 1) ? out : nullptr);

    tok_kernel<<<BT, 256>>>(idx, tok);
    embed_kernel<<<BT, 256>>>(W_emb, tok, x);

    for (int l = 0; l < Ln; l++) {
        ln_kernel<<<BT, 256>>>(x, h);
        gemm_tf32_kernel<<<dim3(D3 / 128, BT / 128), 256>>>(
            h, W_attn + (size_t)l * D3 * Dn, qkv, BT, D3, Dn);
        attn_kernel<<<dim3(Tn / 64, Hn, Bsz), 256>>>(qkv, x);
    }

    ln_kernel<<<BT, 256>>>(x, h);
    gemm_tf32_kernel<<<dim3(Vn / 128, BT / 128), 256>>>(h, W_out, logits, BT, Vn, Dn);

    if (lossp) {
        nll_kernel<<<BT, 256>>>(logits, targets, nll);
        loss_kernel<<<1, 256>>>(nll, lossp);
    }
}

// round 3
// speedup vs baseline: 4.9285x; 3.7820x over previous
#include <cuda_runtime.h>
#include <cstdint>
#include <cstdio>

// Problem constants
#define Bsz 8
#define Tn  1024
#define Vn  8192
#define Dn  1024
#define Hn  16
#define Ln  6
#define HDn 64
#define BT  (Bsz*Tn)      // 8192 rows
#define D3  (3*Dn)        // 3072

// ---------------------------------------------------------------------------
// Scratch
// ---------------------------------------------------------------------------
__device__ float g_x[(size_t)BT * Dn];
__device__ float g_h[(size_t)BT * Dn];
__device__ float g_qkv[(size_t)BT * D3];
__device__ float g_logits_scratch[(size_t)BT * Vn];
__device__ int   g_tok[BT];
__device__ float g_nll[BT];

// ---------------------------------------------------------------------------
// 1. Recover token ids from dense one-hot
// ---------------------------------------------------------------------------
__global__ void __launch_bounds__(256) tok_kernel(const float* __restrict__ idx,
                                                  int* __restrict__ tok) {
    const int row = blockIdx.x;
    const float* r = idx + (size_t)row * Vn;
    for (int v = threadIdx.x; v < Vn; v += 256) {
        if (r[v] > 0.5f) tok[row] = v;
    }
}

// ---------------------------------------------------------------------------
// 2. Embedding gather
// ---------------------------------------------------------------------------
__global__ void __launch_bounds__(256) embed_kernel(const float* __restrict__ W_emb,
                                                    const int* __restrict__ tok,
                                                    float* __restrict__ x) {
    const int row = blockIdx.x;
    const int t = tok[row];
    float* xr = x + (size_t)row * Dn;
    for (int d = threadIdx.x; d < Dn; d += 256)
        xr[d] = W_emb[(size_t)d * Vn + t];
}

// ---------------------------------------------------------------------------
// 3. LayerNorm (parameterless), D=1024
// ---------------------------------------------------------------------------
__global__ void __launch_bounds__(256) ln_kernel(const float* __restrict__ in,
                                                 float* __restrict__ out) {
    const int row = blockIdx.x;
    const float* r = in + (size_t)row * Dn;
    float s = 0.f, ss = 0.f;
    for (int d = threadIdx.x; d < Dn; d += 256) {
        float v = r[d];
        s += v; ss += v * v;
    }
    #pragma unroll
    for (int o = 16; o > 0; o >>= 1) {
        s  += __shfl_xor_sync(0xffffffffu, s,  o);
        ss += __shfl_xor_sync(0xffffffffu, ss, o);
    }
    __shared__ float sb[8], qb[8];
    const int w = threadIdx.x >> 5, lane = threadIdx.x & 31;
    if (lane == 0) { sb[w] = s; qb[w] = ss; }
    __syncthreads();
    float ts = 0.f, tq = 0.f;
    #pragma unroll
    for (int i = 0; i < 8; i++) { ts += sb[i]; tq += qb[i]; }
    const float mu   = ts * (1.0f / Dn);
    const float var  = tq * (1.0f / Dn) - mu * mu;
    const float rstd = rsqrtf(var + 1e-5f);
    float* o2 = out + (size_t)row * Dn;
    for (int d = threadIdx.x; d < Dn; d += 256)
        o2[d] = (r[d] - mu) * rstd;
}

// ---------------------------------------------------------------------------
// tf32 helpers
// ---------------------------------------------------------------------------
__device__ __forceinline__ float f2tf32(float x) {
    uint32_t u;
    asm("cvt.rna.tf32.f32 %0, %1;" : "=r"(u) : "f"(x));
    return __uint_as_float(u);
}

// split x into hi (tf32) + lo (tf32 of remainder); hi+lo ~ x to ~2^-22
__device__ __forceinline__ void split2(float x, uint32_t& hi, uint32_t& lo) {
    asm("cvt.rna.tf32.f32 %0, %1;" : "=r"(hi) : "f"(x));
    float r = x - __uint_as_float(hi);
    asm("cvt.rna.tf32.f32 %0, %1;" : "=r"(lo) : "f"(r));
}

__device__ __forceinline__ void mma_tf32(float* c, const uint32_t* a, const uint32_t* b) {
    asm volatile(
        "mma.sync.aligned.m16n8k8.row.col.f32.tf32.tf32.f32 "
        "{%0,%1,%2,%3}, {%4,%5,%6,%7}, {%8,%9}, {%0,%1,%2,%3};"
        : "+f"(c[0]), "+f"(c[1]), "+f"(c[2]), "+f"(c[3])
        : "r"(a[0]), "r"(a[1]), "r"(a[2]), "r"(a[3]),
          "r"(b[0]), "r"(b[1]));
}

// ---------------------------------------------------------------------------
// 4. tf32 tensor-core GEMM: C[M,N] = A[M,K] * B[N,K]^T (row-major both)
// ---------------------------------------------------------------------------
__global__ void __launch_bounds__(256) gemm_tf32_kernel(
    const float* __restrict__ A, const float* __restrict__ Bm,
    float* __restrict__ C, int M, int N, int K) {
    __shared__ float As[128][36];
    __shared__ float Bs[128][36];

    const int tid  = threadIdx.x;
    const int warp = tid >> 5, lane = tid & 31;
    const int wm = (warp >> 2) * 64;
    const int wn = (warp & 3) * 32;
    const int bx = blockIdx.x, by = blockIdx.y;
    const float* Ab = A  + (size_t)by * 128 * K;
    const float* Bb = Bm + (size_t)bx * 128 * K;

    const int frow = lane >> 2;
    const int fcol = lane & 3;

    float acc[4][4][4];
    #pragma unroll
    for (int i = 0; i < 4; i++)
        #pragma unroll
        for (int j = 0; j < 4; j++)
            #pragma unroll
            for (int v = 0; v < 4; v++) acc[i][j][v] = 0.f;

    float4 ra[4], rb[4];
    #pragma unroll
    for (int i = 0; i < 4; i++) {
        const int id = tid + i * 256;
        const int r = id >> 3, c = (id & 7) << 2;
        ra[i] = *(const float4*)(Ab + (size_t)r * K + c);
        rb[i] = *(const float4*)(Bb + (size_t)r * K + c);
    }

    for (int k0 = 0; k0 < K; k0 += 32) {
        __syncthreads();
        #pragma unroll
        for (int i = 0; i < 4; i++) {
            const int id = tid + i * 256;
            const int r = id >> 3, c = (id & 7) << 2;
            As[r][c + 0] = f2tf32(ra[i].x); As[r][c + 1] = f2tf32(ra[i].y);
            As[r][c + 2] = f2tf32(ra[i].z); As[r][c + 3] = f2tf32(ra[i].w);
            Bs[r][c + 0] = f2tf32(rb[i].x); Bs[r][c + 1] = f2tf32(rb[i].y);
            Bs[r][c + 2] = f2tf32(rb[i].z); Bs[r][c + 3] = f2tf32(rb[i].w);
        }
        __syncthreads();

        if (k0 + 32 < K) {
            #pragma unroll
            for (int i = 0; i < 4; i++) {
                const int id = tid + i * 256;
                const int r = id >> 3, c = (id & 7) << 2;
                ra[i] = *(const float4*)(Ab + (size_t)r * K + k0 + 32 + c);
                rb[i] = *(const float4*)(Bb + (size_t)r * K + k0 + 32 + c);
            }
        }

        #pragma unroll
        for (int kk = 0; kk < 32; kk += 8) {
            uint32_t af[4][4], bf[4][2];
            #pragma unroll
            for (int mi = 0; mi < 4; mi++) {
                const int mr = wm + mi * 16 + frow;
                af[mi][0] = __float_as_uint(As[mr    ][kk + fcol    ]);
                af[mi][1] = __float_as_uint(As[mr + 8][kk + fcol    ]);
                af[mi][2] = __float_as_uint(As[mr    ][kk + fcol + 4]);
                af[mi][3] = __float_as_uint(As[mr + 8][kk + fcol + 4]);
            }
            #pragma unroll
            for (int nj = 0; nj < 4; nj++) {
                const int nr = wn + nj * 8 + frow;
                bf[nj][0] = __float_as_uint(Bs[nr][kk + fcol    ]);
                bf[nj][1] = __float_as_uint(Bs[nr][kk + fcol + 4]);
            }
            #pragma unroll
            for (int mi = 0; mi < 4; mi++)
                #pragma unroll
                for (int nj = 0; nj < 4; nj++)
                    mma_tf32(acc[mi][nj], af[mi], bf[nj]);
        }
    }

    #pragma unroll
    for (int mi = 0; mi < 4; mi++) {
        #pragma unroll
        for (int nj = 0; nj < 4; nj++) {
            const int row = by * 128 + wm + mi * 16 + frow;
            const int col = bx * 128 + wn + nj * 8 + fcol * 2;
            *(float2*)(C + (size_t)row * N + col) =
                make_float2(acc[mi][nj][0], acc[mi][nj][1]);
            *(float2*)(C + (size_t)(row + 8) * N + col) =
                make_float2(acc[mi][nj][2], acc[mi][nj][3]);
        }
    }
}

// ---------------------------------------------------------------------------
// 5. Causal flash attention via split-tf32 mma (fp32-accurate).
//    Block: 128 queries x 1 head x 1 batch; 8 warps, 16 q-rows per warp.
//    KV tiles of 64. Smem raw fp32; split to tf32 hi/lo at fragment load.
//    Stride 68 floats => all fragment LDS patterns bank-conflict-free.
// ---------------------------------------------------------------------------
__global__ void __launch_bounds__(256, 2) attn_mma_kernel(
    const float* __restrict__ qkv, float* __restrict__ x) {
    extern __shared__ float sm[];
    float* Qs = sm;                        // [128][68]
    float* Ks = Qs + 128 * 68;             // [64][68]
    float* Vs = Ks + 64 * 68;              // [64][68]
    float* Ps = Vs + 64 * 68;              // [128][68]

    const int qt = blockIdx.x;             // 0..7 (128-row q tiles)
    const int h  = blockIdx.y;
    const int b  = blockIdx.z;
    const int tid = threadIdx.x;
    const int w = tid >> 5, lane = tid & 31;
    const int gid = lane >> 2, tig = lane & 3;
    const size_t base3 = (size_t)b * Tn * D3;
    const int hoff = h * HDn;

    // load Q tile [128][64]
    #pragma unroll
    for (int it = 0; it < 8; it++) {
        const int i = tid + it * 256;
        const int r = i >> 4, c4 = (i & 15) << 2;
        float4 v = *(const float4*)&qkv[base3 + (size_t)(qt * 128 + r) * D3 + hoff + c4];
        float* d = &Qs[r * 68 + c4];
        d[0] = v.x; d[1] = v.y; d[2] = v.z; d[3] = v.w;
    }

    float m0 = -1e30f, m1 = -1e30f, l0 = 0.f, l1 = 0.f;
    float accO[8][4];
    #pragma unroll
    for (int nt = 0; nt < 8; nt++)
        #pragma unroll
        for (int v = 0; v < 4; v++) accO[nt][v] = 0.f;

    const int prow = w * 16 + gid;          // warp-local P row (this thread's row0)
    const int r0g = qt * 128 + prow;        // global query positions
    const int r1g = r0g + 8;
    const int jt_end = 2 * qt + 1;

    for (int jt = 0; jt <= jt_end; jt++) {
        __syncthreads();    // prior tile's K/V reads done (and Q store visible)
        #pragma unroll
        for (int it = 0; it < 4; it++) {
            const int i = tid + it * 256;
            const int r = i >> 4, c4 = (i & 15) << 2;
            const size_t g = base3 + (size_t)(jt * 64 + r) * D3 + hoff + c4;
            float4 k4 = *(const float4*)&qkv[g + Dn];
            float4 v4 = *(const float4*)&qkv[g + 2 * Dn];
            float* dk = &Ks[r * 68 + c4];
            dk[0] = k4.x; dk[1] = k4.y; dk[2] = k4.z; dk[3] = k4.w;
            float* dv = &Vs[r * 68 + c4];
            dv[0] = v4.x; dv[1] = v4.y; dv[2] = v4.z; dv[3] = v4.w;
        }
        __syncthreads();

        // --- scores: S = Q K^T (split-tf32, 3 mmas) ---
        float accS[8][4];
        #pragma unroll
        for (int nt = 0; nt < 8; nt++)
            #pragma unroll
            for (int v = 0; v < 4; v++) accS[nt][v] = 0.f;

        #pragma unroll
        for (int kc = 0; kc < 8; kc++) {
            uint32_t ah[4], al[4];
            split2(Qs[prow * 68 + kc * 8 + tig],           ah[0], al[0]);
            split2(Qs[(prow + 8) * 68 + kc * 8 + tig],     ah[1], al[1]);
            split2(Qs[prow * 68 + kc * 8 + tig + 4],       ah[2], al[2]);
            split2(Qs[(prow + 8) * 68 + kc * 8 + tig + 4], ah[3], al[3]);
            #pragma unroll
            for (int nt = 0; nt < 8; nt++) {
                uint32_t bh[2], bl[2];
                split2(Ks[(nt * 8 + gid) * 68 + kc * 8 + tig],     bh[0], bl[0]);
                split2(Ks[(nt * 8 + gid) * 68 + kc * 8 + tig + 4], bh[1], bl[1]);
                mma_tf32(accS[nt], ah, bh);
                mma_tf32(accS[nt], ah, bl);
                mma_tf32(accS[nt], al, bh);
            }
        }

        // --- scale + causal mask (only needed near the diagonal) ---
        const bool diag = (jt * 64 + 63 > qt * 128);
        #pragma unroll
        for (int nt = 0; nt < 8; nt++) {
            const int c0 = jt * 64 + nt * 8 + 2 * tig;
            accS[nt][0] *= 0.125f; accS[nt][1] *= 0.125f;
            accS[nt][2] *= 0.125f; accS[nt][3] *= 0.125f;
            if (diag) {
                if (c0     > r0g) accS[nt][0] = -1e30f;
                if (c0 + 1 > r0g) accS[nt][1] = -1e30f;
                if (c0     > r1g) accS[nt][2] = -1e30f;
                if (c0 + 1 > r1g) accS[nt][3] = -1e30f;
            }
        }

        // --- online softmax (rows r0, r1 per thread; 4-lane groups share rows) ---
        float tm0 = -1e30f, tm1 = -1e30f;
        #pragma unroll
        for (int nt = 0; nt < 8; nt++) {
            tm0 = fmaxf(tm0, fmaxf(accS[nt][0], accS[nt][1]));
            tm1 = fmaxf(tm1, fmaxf(accS[nt][2], accS[nt][3]));
        }
        tm0 = fmaxf(tm0, __shfl_xor_sync(0xffffffffu, tm0, 1));
        tm0 = fmaxf(tm0, __shfl_xor_sync(0xffffffffu, tm0, 2));
        tm1 = fmaxf(tm1, __shfl_xor_sync(0xffffffffu, tm1, 1));
        tm1 = fmaxf(tm1, __shfl_xor_sync(0xffffffffu, tm1, 2));
        const float nm0 = fmaxf(m0, tm0), nm1 = fmaxf(m1, tm1);
        const float corr0 = __expf(m0 - nm0), corr1 = __expf(m1 - nm1);
        m0 = nm0; m1 = nm1;
        float ts0 = 0.f, ts1 = 0.f;
        #pragma unroll
        for (int nt = 0; nt < 8; nt++) {
            accS[nt][0] = __expf(accS[nt][0] - nm0);
            accS[nt][1] = __expf(accS[nt][1] - nm0);
            accS[nt][2] = __expf(accS[nt][2] - nm1);
            accS[nt][3] = __expf(accS[nt][3] - nm1);
            ts0 += accS[nt][0] + accS[nt][1];
            ts1 += accS[nt][2] + accS[nt][3];
        }
        ts0 += __shfl_xor_sync(0xffffffffu, ts0, 1);
        ts0 += __shfl_xor_sync(0xffffffffu, ts0, 2);
        ts1 += __shfl_xor_sync(0xffffffffu, ts1, 1);
        ts1 += __shfl_xor_sync(0xffffffffu, ts1, 2);
        l0 = l0 * corr0 + ts0;
        l1 = l1 * corr1 + ts1;
        #pragma unroll
        for (int nt = 0; nt < 8; nt++) {
            accO[nt][0] *= corr0; accO[nt][1] *= corr0;
            accO[nt][2] *= corr1; accO[nt][3] *= corr1;
        }

        // --- write P (own rows only) ---
        #pragma unroll
        for (int nt = 0; nt < 8; nt++) {
            *(float2*)&Ps[prow * 68 + nt * 8 + 2 * tig] =
                make_float2(accS[nt][0], accS[nt][1]);
            *(float2*)&Ps[(prow + 8) * 68 + nt * 8 + 2 * tig] =
                make_float2(accS[nt][2], accS[nt][3]);
        }
        __syncwarp();

        // --- O += P V (split-tf32, 3 mmas) ---
        #pragma unroll
        for (int kc = 0; kc < 8; kc++) {
            uint32_t ah[4], al[4];
            split2(Ps[prow * 68 + kc * 8 + tig],           ah[0], al[0]);
            split2(Ps[(prow + 8) * 68 + kc * 8 + tig],     ah[1], al[1]);
            split2(Ps[prow * 68 + kc * 8 + tig + 4],       ah[2], al[2]);
            split2(Ps[(prow + 8) * 68 + kc * 8 + tig + 4], ah[3], al[3]);
            #pragma unroll
            for (int nt = 0; nt < 8; nt++) {
                uint32_t bh[2], bl[2];
                split2(Vs[(kc * 8 + tig) * 68 + nt * 8 + gid],     bh[0], bl[0]);
                split2(Vs[(kc * 8 + tig + 4) * 68 + nt * 8 + gid], bh[1], bl[1]);
                mma_tf32(accO[nt], ah, bh);
                mma_tf32(accO[nt], ah, bl);
                mma_tf32(accO[nt], al, bh);
            }
        }
    }

    // --- epilogue: x += O / l ---
    const float inv0 = 1.0f / l0, inv1 = 1.0f / l1;
    #pragma unroll
    for (int nt = 0; nt < 8; nt++) {
        const int col = hoff + nt * 8 + 2 * tig;
        float* p0 = &x[((size_t)b * Tn + r0g) * Dn + col];
        p0[0] += accO[nt][0] * inv0;
        p0[1] += accO[nt][1] * inv0;
        float* p1 = &x[((size_t)b * Tn + r1g) * Dn + col];
        p1[0] += accO[nt][2] * inv1;
        p1[1] += accO[nt][3] * inv1;
    }
}

// ---------------------------------------------------------------------------
// 6. Per-row NLL
// ---------------------------------------------------------------------------
__global__ void __launch_bounds__(256) nll_kernel(const float* __restrict__ logits,
                                                  const int* __restrict__ targets,
                                                  float* __restrict__ nll) {
    const int row = blockIdx.x;
    const float* r = logits + (size_t)row * Vn;
    float mx = -3.0e38f;
    for (int v = threadIdx.x; v < Vn; v += 256) mx = fmaxf(mx, r[v]);
    #pragma unroll
    for (int o = 16; o > 0; o >>= 1) mx = fmaxf(mx, __shfl_xor_sync(0xffffffffu, mx, o));
    __shared__ float mb[8];
    __shared__ float sbuf[8];
    const int w = threadIdx.x >> 5, lane = threadIdx.x & 31;
    if (lane == 0) mb[w] = mx;
    __syncthreads();
    float gm = mb[0];
    #pragma unroll
    for (int i = 1; i < 8; i++) gm = fmaxf(gm, mb[i]);

    float se = 0.f;
    for (int v = threadIdx.x; v < Vn; v += 256) se += __expf(r[v] - gm);
    #pragma unroll
    for (int o = 16; o > 0; o >>= 1) se += __shfl_xor_sync(0xffffffffu, se, o);
    if (lane == 0) sbuf[w] = se;
    __syncthreads();
    if (threadIdx.x == 0) {
        float tot = 0.f;
        #pragma unroll
        for (int i = 0; i < 8; i++) tot += sbuf[i];
        nll[row] = gm + logf(tot) - r[targets[row]];
    }
}

// ---------------------------------------------------------------------------
// 7. Mean over row NLLs
// ---------------------------------------------------------------------------
__global__ void __launch_bounds__(256) loss_kernel(const float* __restrict__ nll,
                                                   float* __restrict__ out) {
    float s = 0.f;
    for (int i = threadIdx.x; i < BT; i += 256) s += nll[i];
    #pragma unroll
    for (int o = 16; o > 0; o >>= 1) s += __shfl_xor_sync(0xffffffffu, s, o);
    __shared__ float sb[8];
    const int w = threadIdx.x >> 5, lane = threadIdx.x & 31;
    if (lane == 0) sb[w] = s;
    __syncthreads();
    if (threadIdx.x == 0) {
        float tot = 0.f;
        #pragma unroll
        for (int i = 0; i < 8; i++) tot += sb[i];
        out[0] = tot * (1.0f / BT);
    }
}

// ---------------------------------------------------------------------------
// Host entry
// ---------------------------------------------------------------------------
#define ATTN_SMEM ((128*68 + 64*68 + 64*68 + 128*68) * 4)

extern "C" void kernel_launch(void* const* d_in, const int* in_sizes, int n_in,
                              void* d_out, int out_size) {
    (void)in_sizes; (void)n_in;
    const float* idx     = (const float*)d_in[0];
    const int*   targets = (const int*)d_in[1];
    const float* W_emb   = (const float*)d_in[2];
    const float* W_attn  = (const float*)d_in[3];
    const float* W_out   = (const float*)d_in[4];
    float* out = (float*)d_out;

    float *x, *h, *qkv, *nll, *lscr;
    int* tok;
    cudaGetSymbolAddress((void**)&x,    g_x);
    cudaGetSymbolAddress((void**)&h,    g_h);
    cudaGetSymbolAddress((void**)&qkv,  g_qkv);
    cudaGetSymbolAddress((void**)&nll,  g_nll);
    cudaGetSymbolAddress((void**)&lscr, g_logits_scratch);
    cudaGetSymbolAddress((void**)&tok,  g_tok);

    cudaFuncSetAttribute(attn_mma_kernel,
                         cudaFuncAttributeMaxDynamicSharedMemorySize, ATTN_SMEM);

    const size_t BTV = (size_t)BT * Vn;
    float* logits = ((size_t)out_size >= BTV) ? out : lscr;
    float* lossp  = ((size_t)out_size > BTV) ? (out + BTV)
                  : ((out_size == 1) ? out : nullptr);

    tok_kernel<<<BT, 256>>>(idx, tok);
    embed_kernel<<<BT, 256>>>(W_emb, tok, x);

    for (int l = 0; l < Ln; l++) {
        ln_kernel<<<BT, 256>>>(x, h);
        gemm_tf32_kernel<<<dim3(D3 / 128, BT / 128), 256>>>(
            h, W_attn + (size_t)l * D3 * Dn, qkv, BT, D3, Dn);
        attn_mma_kernel<<<dim3(Tn / 128, Hn, Bsz), 256, ATTN_SMEM>>>(qkv, x);
    }

    ln_kernel<<<BT, 256>>>(x, h);
    gemm_tf32_kernel<<<dim3(Vn / 128, BT / 128), 256>>>(h, W_out, logits, BT, Vn, Dn);

    if (lossp) {
        nll_kernel<<<BT, 256>>>(logits, targets, nll);
        loss_kernel<<<1, 256>>>(nll, lossp);
    }
}

// round 5
// speedup vs baseline: 5.2375x; 1.0627x over previous
#include <cuda_runtime.h>
#include <cstdint>
#include <cstdio>

// Problem constants
#define Bsz 8
#define Tn  1024
#define Vn  8192
#define Dn  1024
#define Hn  16
#define Ln  6
#define HDn 64
#define BT  (Bsz*Tn)      // 8192 rows
#define D3  (3*Dn)        // 3072

// ---------------------------------------------------------------------------
// Scratch
// ---------------------------------------------------------------------------
__device__ float g_x[(size_t)BT * Dn];
__device__ float g_h[(size_t)BT * Dn];
__device__ float g_qkv[(size_t)BT * D3];
__device__ float g_logits_scratch[(size_t)BT * Vn];
__device__ float g_wattn_r[(size_t)Ln * D3 * Dn];   // tf32-rounded W_attn
__device__ float g_wout_r[(size_t)Vn * Dn];         // tf32-rounded W_out
__device__ int   g_tok[BT];
__device__ float g_nll[BT];

// ---------------------------------------------------------------------------
// tf32 helpers
// ---------------------------------------------------------------------------
__device__ __forceinline__ float f2tf32(float x) {
    uint32_t u;
    asm("cvt.rna.tf32.f32 %0, %1;" : "=r"(u) : "f"(x));
    return __uint_as_float(u);
}

__device__ __forceinline__ void split2(float x, uint32_t& hi, uint32_t& lo) {
    asm("cvt.rna.tf32.f32 %0, %1;" : "=r"(hi) : "f"(x));
    float r = x - __uint_as_float(hi);
    asm("cvt.rna.tf32.f32 %0, %1;" : "=r"(lo) : "f"(r));
}

__device__ __forceinline__ void mma_tf32(float* c, const uint32_t* a, const uint32_t* b) {
    asm volatile(
        "mma.sync.aligned.m16n8k8.row.col.f32.tf32.tf32.f32 "
        "{%0,%1,%2,%3}, {%4,%5,%6,%7}, {%8,%9}, {%0,%1,%2,%3};"
        : "+f"(c[0]), "+f"(c[1]), "+f"(c[2]), "+f"(c[3])
        : "r"(a[0]), "r"(a[1]), "r"(a[2]), "r"(a[3]),
          "r"(b[0]), "r"(b[1]));
}

// ---------------------------------------------------------------------------
// cp.async primitives
// ---------------------------------------------------------------------------
__device__ __forceinline__ uint32_t smem_u32(const void* p) {
    uint32_t a;
    asm("{ .reg .u64 t; cvta.to.shared.u64 t, %1; cvt.u32.u64 %0, t; }"
        : "=r"(a) : "l"(p));
    return a;
}
__device__ __forceinline__ void cp_async16(uint32_t dst, const void* src) {
    asm volatile("cp.async.cg.shared.global [%0], [%1], 16;" :: "r"(dst), "l"(src));
}
__device__ __forceinline__ void cp_commit() {
    asm volatile("cp.async.commit_group;" ::: "memory");
}
template <int N> __device__ __forceinline__ void cp_wait() {
    asm volatile("cp.async.wait_group %0;" :: "n"(N) : "memory");
}

// ---------------------------------------------------------------------------
// 0. Round weights to tf32 (rna): then raw copies into smem feed mma exactly
// ---------------------------------------------------------------------------
__global__ void __launch_bounds__(256) round_tf32_kernel(const float4* __restrict__ in,
                                                         float4* __restrict__ out, int n4) {
    for (int i = blockIdx.x * 256 + threadIdx.x; i < n4; i += gridDim.x * 256) {
        float4 v = in[i];
        out[i] = make_float4(f2tf32(v.x), f2tf32(v.y), f2tf32(v.z), f2tf32(v.w));
    }
}

// ---------------------------------------------------------------------------
// 1. Token ids from one-hot
// ---------------------------------------------------------------------------
__global__ void __launch_bounds__(256) tok_kernel(const float* __restrict__ idx,
                                                  int* __restrict__ tok) {
    const int row = blockIdx.x;
    const float* r = idx + (size_t)row * Vn;
    for (int v = threadIdx.x; v < Vn; v += 256) {
        if (r[v] > 0.5f) tok[row] = v;
    }
}

// ---------------------------------------------------------------------------
// 2. Embedding gather
// ---------------------------------------------------------------------------
__global__ void __launch_bounds__(256) embed_kernel(const float* __restrict__ W_emb,
                                                    const int* __restrict__ tok,
                                                    float* __restrict__ x) {
    const int row = blockIdx.x;
    const int t = tok[row];
    float* xr = x + (size_t)row * Dn;
    for (int d = threadIdx.x; d < Dn; d += 256)
        xr[d] = W_emb[(size_t)d * Vn + t];
}

// ---------------------------------------------------------------------------
// 3. LayerNorm; output rounded to tf32 (it only feeds GEMM A operand)
// ---------------------------------------------------------------------------
__global__ void __launch_bounds__(256) ln_kernel(const float* __restrict__ in,
                                                 float* __restrict__ out) {
    const int row = blockIdx.x;
    const float* r = in + (size_t)row * Dn;
    float s = 0.f, ss = 0.f;
    for (int d = threadIdx.x; d < Dn; d += 256) {
        float v = r[d];
        s += v; ss += v * v;
    }
    #pragma unroll
    for (int o = 16; o > 0; o >>= 1) {
        s  += __shfl_xor_sync(0xffffffffu, s,  o);
        ss += __shfl_xor_sync(0xffffffffu, ss, o);
    }
    __shared__ float sb[8], qb[8];
    const int w = threadIdx.x >> 5, lane = threadIdx.x & 31;
    if (lane == 0) { sb[w] = s; qb[w] = ss; }
    __syncthreads();
    float ts = 0.f, tq = 0.f;
    #pragma unroll
    for (int i = 0; i < 8; i++) { ts += sb[i]; tq += qb[i]; }
    const float mu   = ts * (1.0f / Dn);
    const float var  = tq * (1.0f / Dn) - mu * mu;
    const float rstd = rsqrtf(var + 1e-5f);
    float* o2 = out + (size_t)row * Dn;
    for (int d = threadIdx.x; d < Dn; d += 256)
        o2[d] = f2tf32((r[d] - mu) * rstd);
}

// ---------------------------------------------------------------------------
// 4. tf32 HMMA GEMM with cp.async 3-stage pipeline.
//    C[M,N] = A[M,K]*B[N,K]^T, tiles 128x128, BK=32, K=1024.
//    Inputs MUST be tf32-rna pre-rounded (raw copy == exact tf32 operand).
// ---------------------------------------------------------------------------
#define GS 3
#define G_TILE (128 * 36)                  // floats per As or Bs stage half
#define G_STAGEF (2 * G_TILE)              // floats per stage
#define G_SMEM (GS * G_STAGEF * 4)         // bytes
#define G_NCH (Dn / 32)                    // 32 chunks

__global__ void __launch_bounds__(256) gemm_tf32_cp_kernel(
    const float* __restrict__ A, const float* __restrict__ Bm,
    float* __restrict__ C, int N) {
    extern __shared__ float gsm[];
    const uint32_t smb = smem_u32(gsm);

    const int tid  = threadIdx.x;
    const int warp = tid >> 5, lane = tid & 31;
    const int wm = (warp >> 2) * 64;
    const int wn = (warp & 3) * 32;
    const int frow = lane >> 2;
    const int fcol = lane & 3;

    const float* Ab = A  + (size_t)blockIdx.y * 128 * Dn;
    const float* Bb = Bm + (size_t)blockIdx.x * 128 * Dn;

    // staging coords: 4 rows-groups per matrix, 8 threads per row
    const int sr = tid >> 3;                 // 0..31 base row
    const int sc = (tid & 7) << 2;           // float col group

    auto load_chunk = [&](int chunk, int stage) {
        const uint32_t abase = smb + (uint32_t)(stage * G_STAGEF) * 4;
        const uint32_t bbase = abase + G_TILE * 4;
        const size_t kof = (size_t)chunk * 32 + sc;
        #pragma unroll
        for (int i = 0; i < 4; i++) {
            const int r = sr + i * 32;
            cp_async16(abase + (uint32_t)(r * 36 + sc) * 4, Ab + (size_t)r * Dn + kof);
            cp_async16(bbase + (uint32_t)(r * 36 + sc) * 4, Bb + (size_t)r * Dn + kof);
        }
    };

    float acc[4][4][4];
    #pragma unroll
    for (int i = 0; i < 4; i++)
        #pragma unroll
        for (int j = 0; j < 4; j++)
            #pragma unroll
            for (int v = 0; v < 4; v++) acc[i][j][v] = 0.f;

    load_chunk(0, 0); cp_commit();
    load_chunk(1, 1); cp_commit();

    for (int c = 0; c < G_NCH; c++) {
        if (c + 2 < G_NCH) { load_chunk(c + 2, (c + 2) % GS); cp_commit(); }
        const int rem = G_NCH - 1 - c;
        if (rem >= 2)      cp_wait<2>();
        else if (rem == 1) cp_wait<1>();
        else               cp_wait<0>();
        __syncthreads();

        const float* As = gsm + (c % GS) * G_STAGEF;
        const float* Bs = As + G_TILE;

        #pragma unroll
        for (int kk = 0; kk < 32; kk += 8) {
            uint32_t af[4][4], bf[4][2];
            #pragma unroll
            for (int mi = 0; mi < 4; mi++) {
                const int mr = wm + mi * 16 + frow;
                af[mi][0] = __float_as_uint(As[mr * 36 + kk + fcol]);
                af[mi][1] = __float_as_uint(As[(mr + 8) * 36 + kk + fcol]);
                af[mi][2] = __float_as_uint(As[mr * 36 + kk + fcol + 4]);
                af[mi][3] = __float_as_uint(As[(mr + 8) * 36 + kk + fcol + 4]);
            }
            #pragma unroll
            for (int nj = 0; nj < 4; nj++) {
                const int nr = wn + nj * 8 + frow;
                bf[nj][0] = __float_as_uint(Bs[nr * 36 + kk + fcol]);
                bf[nj][1] = __float_as_uint(Bs[nr * 36 + kk + fcol + 4]);
            }
            #pragma unroll
            for (int mi = 0; mi < 4; mi++)
                #pragma unroll
                for (int nj = 0; nj < 4; nj++)
                    mma_tf32(acc[mi][nj], af[mi], bf[nj]);
        }
        __syncthreads();
    }

    #pragma unroll
    for (int mi = 0; mi < 4; mi++) {
        #pragma unroll
        for (int nj = 0; nj < 4; nj++) {
            const int row = blockIdx.y * 128 + wm + mi * 16 + frow;
            const int col = blockIdx.x * 128 + wn + nj * 8 + fcol * 2;
            *(float2*)(C + (size_t)row * N + col) =
                make_float2(acc[mi][nj][0], acc[mi][nj][1]);
            *(float2*)(C + (size_t)(row + 8) * N + col) =
                make_float2(acc[mi][nj][2], acc[mi][nj][3]);
        }
    }
}

// ---------------------------------------------------------------------------
// 5. Causal flash attention, split-tf32 mma, K/V pre-split into (hi,lo) f2.
//    Block: 128 q-rows x head x batch, 8 warps. KV tiles of 32 rows.
//    Smem: Q[128][68]f + P[128][36]f + Khl[32][68]f2 + Vhl[32][68]f2 = 88KB.
// ---------------------------------------------------------------------------
#define AQ 68
#define AP 36
#define AK 68   // float2 stride
#define ATTN_SMEM ((128*AQ + 128*AP + 32*AK*2 + 32*AK*2) * 4)

__global__ void __launch_bounds__(256, 2) attn_mma_kernel(
    const float* __restrict__ qkv, float* __restrict__ x) {
    extern __shared__ float sm[];
    float*  Qs  = sm;                                  // [128][68]
    float*  Ps  = Qs + 128 * AQ;                       // [128][36]
    float2* Khl = (float2*)(Ps + 128 * AP);            // [32][68]
    float2* Vhl = Khl + 32 * AK;                       // [32][68]

    const int qt = blockIdx.x;             // 0..7
    const int h  = blockIdx.y;
    const int b  = blockIdx.z;
    const int tid = threadIdx.x;
    const int w = tid >> 5, lane = tid & 31;
    const int gid = lane >> 2, tig = lane & 3;
    const size_t base3 = (size_t)b * Tn * D3;
    const int hoff = h * HDn;

    // load Q tile [128][64]
    #pragma unroll
    for (int it = 0; it < 8; it++) {
        const int i = tid + it * 256;
        const int r = i >> 4, c4 = (i & 15) << 2;
        float4 v = *(const float4*)&qkv[base3 + (size_t)(qt * 128 + r) * D3 + hoff + c4];
        float* d = &Qs[r * AQ + c4];
        d[0] = v.x; d[1] = v.y; d[2] = v.z; d[3] = v.w;
    }

    float m0 = -1e30f, m1 = -1e30f, l0 = 0.f, l1 = 0.f;
    float accO[8][4];
    #pragma unroll
    for (int nt = 0; nt < 8; nt++)
        #pragma unroll
        for (int v = 0; v < 4; v++) accO[nt][v] = 0.f;

    const int prow = w * 16 + gid;
    const int r0g = qt * 128 + prow;
    const int r1g = r0g + 8;
    const int jt_end = 4 * qt + 3;

    for (int jt = 0; jt <= jt_end; jt++) {
        __syncthreads();    // prior tile consumed (& Q visible on iter 0)
        // load K/V [32][64], split to (hi,lo) at load
        #pragma unroll
        for (int it = 0; it < 2; it++) {
            const int i = tid + it * 256;
            const int r = i >> 4, c4 = (i & 15) << 2;
            const size_t g = base3 + (size_t)(jt * 32 + r) * D3 + hoff + c4;
            float4 k4 = *(const float4*)&qkv[g + Dn];
            float4 v4 = *(const float4*)&qkv[g + 2 * Dn];
            uint32_t hi, lo;
            float2* dk = &Khl[r * AK + c4];
            split2(k4.x, hi, lo); dk[0] = make_float2(__uint_as_float(hi), __uint_as_float(lo));
            split2(k4.y, hi, lo); dk[1] = make_float2(__uint_as_float(hi), __uint_as_float(lo));
            split2(k4.z, hi, lo); dk[2] = make_float2(__uint_as_float(hi), __uint_as_float(lo));
            split2(k4.w, hi, lo); dk[3] = make_float2(__uint_as_float(hi), __uint_as_float(lo));
            float2* dv = &Vhl[r * AK + c4];
            split2(v4.x, hi, lo); dv[0] = make_float2(__uint_as_float(hi), __uint_as_float(lo));
            split2(v4.y, hi, lo); dv[1] = make_float2(__uint_as_float(hi), __uint_as_float(lo));
            split2(v4.z, hi, lo); dv[2] = make_float2(__uint_as_float(hi), __uint_as_float(lo));
            split2(v4.w, hi, lo); dv[3] = make_float2(__uint_as_float(hi), __uint_as_float(lo));
        }
        __syncthreads();

        // --- S = Q K^T (split-tf32, 3 mmas) ---
        float accS[4][4];
        #pragma unroll
        for (int nt = 0; nt < 4; nt++)
            #pragma unroll
            for (int v = 0; v < 4; v++) accS[nt][v] = 0.f;

        #pragma unroll
        for (int kc = 0; kc < 8; kc++) {
            uint32_t ah[4], al[4];
            split2(Qs[prow * AQ + kc * 8 + tig],           ah[0], al[0]);
            split2(Qs[(prow + 8) * AQ + kc * 8 + tig],     ah[1], al[1]);
            split2(Qs[prow * AQ + kc * 8 + tig + 4],       ah[2], al[2]);
            split2(Qs[(prow + 8) * AQ + kc * 8 + tig + 4], ah[3], al[3]);
            #pragma unroll
            for (int nt = 0; nt < 4; nt++) {
                const float2 k0 = Khl[(nt * 8 + gid) * AK + kc * 8 + tig];
                const float2 k1 = Khl[(nt * 8 + gid) * AK + kc * 8 + tig + 4];
                uint32_t bh[2] = { __float_as_uint(k0.x), __float_as_uint(k1.x) };
                uint32_t bl[2] = { __float_as_uint(k0.y), __float_as_uint(k1.y) };
                mma_tf32(accS[nt], ah, bh);
                mma_tf32(accS[nt], ah, bl);
                mma_tf32(accS[nt], al, bh);
            }
        }

        // --- scale + causal mask ---
        const bool diag = (jt >= 4 * qt);
        #pragma unroll
        for (int nt = 0; nt < 4; nt++) {
            const int c0 = jt * 32 + nt * 8 + 2 * tig;
            accS[nt][0] *= 0.125f; accS[nt][1] *= 0.125f;
            accS[nt][2] *= 0.125f; accS[nt][3] *= 0.125f;
            if (diag) {
                if (c0     > r0g) accS[nt][0] = -1e30f;
                if (c0 + 1 > r0g) accS[nt][1] = -1e30f;
                if (c0     > r1g) accS[nt][2] = -1e30f;
                if (c0 + 1 > r1g) accS[nt][3] = -1e30f;
            }
        }

        // --- online softmax ---
        float tm0 = -1e30f, tm1 = -1e30f;
        #pragma unroll
        for (int nt = 0; nt < 4; nt++) {
            tm0 = fmaxf(tm0, fmaxf(accS[nt][0], accS[nt][1]));
            tm1 = fmaxf(tm1, fmaxf(accS[nt][2], accS[nt][3]));
        }
        tm0 = fmaxf(tm0, __shfl_xor_sync(0xffffffffu, tm0, 1));
        tm0 = fmaxf(tm0, __shfl_xor_sync(0xffffffffu, tm0, 2));
        tm1 = fmaxf(tm1, __shfl_xor_sync(0xffffffffu, tm1, 1));
        tm1 = fmaxf(tm1, __shfl_xor_sync(0xffffffffu, tm1, 2));
        const float nm0 = fmaxf(m0, tm0), nm1 = fmaxf(m1, tm1);
        const float corr0 = __expf(m0 - nm0), corr1 = __expf(m1 - nm1);
        m0 = nm0; m1 = nm1;
        float ts0 = 0.f, ts1 = 0.f;
        #pragma unroll
        for (int nt = 0; nt < 4; nt++) {
            accS[nt][0] = __expf(accS[nt][0] - nm0);
            accS[nt][1] = __expf(accS[nt][1] - nm0);
            accS[nt][2] = __expf(accS[nt][2] - nm1);
            accS[nt][3] = __expf(accS[nt][3] - nm1);
            ts0 += accS[nt][0] + accS[nt][1];
            ts1 += accS[nt][2] + accS[nt][3];
        }
        ts0 += __shfl_xor_sync(0xffffffffu, ts0, 1);
        ts0 += __shfl_xor_sync(0xffffffffu, ts0, 2);
        ts1 += __shfl_xor_sync(0xffffffffu, ts1, 1);
        ts1 += __shfl_xor_sync(0xffffffffu, ts1, 2);
        l0 = l0 * corr0 + ts0;
        l1 = l1 * corr1 + ts1;
        #pragma unroll
        for (int nt = 0; nt < 8; nt++) {
            accO[nt][0] *= corr0; accO[nt][1] *= corr0;
            accO[nt][2] *= corr1; accO[nt][3] *= corr1;
        }

        // --- write P (own rows only), then PV ---
        #pragma unroll
        for (int nt = 0; nt < 4; nt++) {
            *(float2*)&Ps[prow * AP + nt * 8 + 2 * tig] =
                make_float2(accS[nt][0], accS[nt][1]);
            *(float2*)&Ps[(prow + 8) * AP + nt * 8 + 2 * tig] =
                make_float2(accS[nt][2], accS[nt][3]);
        }
        __syncwarp();

        #pragma unroll
        for (int kc = 0; kc < 4; kc++) {
            uint32_t ah[4], al[4];
            split2(Ps[prow * AP + kc * 8 + tig],           ah[0], al[0]);
            split2(Ps[(prow + 8) * AP + kc * 8 + tig],     ah[1], al[1]);
            split2(Ps[prow * AP + kc * 8 + tig + 4],       ah[2], al[2]);
            split2(Ps[(prow + 8) * AP + kc * 8 + tig + 4], ah[3], al[3]);
            #pragma unroll
            for (int nt = 0; nt < 8; nt++) {
                const float2 v0 = Vhl[(kc * 8 + tig) * AK + nt * 8 + gid];
                const float2 v1 = Vhl[(kc * 8 + tig + 4) * AK + nt * 8 + gid];
                uint32_t bh[2] = { __float_as_uint(v0.x), __float_as_uint(v1.x) };
                uint32_t bl[2] = { __float_as_uint(v0.y), __float_as_uint(v1.y) };
                mma_tf32(accO[nt], ah, bh);
                mma_tf32(accO[nt], ah, bl);
                mma_tf32(accO[nt], al, bh);
            }
        }
    }

    // --- epilogue: x += O / l ---
    const float inv0 = 1.0f / l0, inv1 = 1.0f / l1;
    #pragma unroll
    for (int nt = 0; nt < 8; nt++) {
        const int col = hoff + nt * 8 + 2 * tig;
        float* p0 = &x[((size_t)b * Tn + r0g) * Dn + col];
        p0[0] += accO[nt][0] * inv0;
        p0[1] += accO[nt][1] * inv0;
        float* p1 = &x[((size_t)b * Tn + r1g) * Dn + col];
        p1[0] += accO[nt][2] * inv1;
        p1[1] += accO[nt][3] * inv1;
    }
}

// ---------------------------------------------------------------------------
// 6. Per-row NLL
// ---------------------------------------------------------------------------
__global__ void __launch_bounds__(256) nll_kernel(const float* __restrict__ logits,
                                                  const int* __restrict__ targets,
                                                  float* __restrict__ nll) {
    const int row = blockIdx.x;
    const float* r = logits + (size_t)row * Vn;
    float mx = -3.0e38f;
    for (int v = threadIdx.x; v < Vn; v += 256) mx = fmaxf(mx, r[v]);
    #pragma unroll
    for (int o = 16; o > 0; o >>= 1) mx = fmaxf(mx, __shfl_xor_sync(0xffffffffu, mx, o));
    __shared__ float mb[8];
    __shared__ float sbuf[8];
    const int w = threadIdx.x >> 5, lane = threadIdx.x & 31;
    if (lane == 0) mb[w] = mx;
    __syncthreads();
    float gm = mb[0];
    #pragma unroll
    for (int i = 1; i < 8; i++) gm = fmaxf(gm, mb[i]);

    float se = 0.f;
    for (int v = threadIdx.x; v < Vn; v += 256) se += __expf(r[v] - gm);
    #pragma unroll
    for (int o = 16; o > 0; o >>= 1) se += __shfl_xor_sync(0xffffffffu, se, o);
    if (lane == 0) sbuf[w] = se;
    __syncthreads();
    if (threadIdx.x == 0) {
        float tot = 0.f;
        #pragma unroll
        for (int i = 0; i < 8; i++) tot += sbuf[i];
        nll[row] = gm + logf(tot) - r[targets[row]];
    }
}

// ---------------------------------------------------------------------------
// 7. Mean over row NLLs
// ---------------------------------------------------------------------------
__global__ void __launch_bounds__(256) loss_kernel(const float* __restrict__ nll,
                                                   float* __restrict__ out) {
    float s = 0.f;
    for (int i = threadIdx.x; i < BT; i += 256) s += nll[i];
    #pragma unroll
    for (int o = 16; o > 0; o >>= 1) s += __shfl_xor_sync(0xffffffffu, s, o);
    __shared__ float sb[8];
    const int w = threadIdx.x >> 5, lane = threadIdx.x & 31;
    if (lane == 0) sb[w] = s;
    __syncthreads();
    if (threadIdx.x == 0) {
        float tot = 0.f;
        #pragma unroll
        for (int i = 0; i < 8; i++) tot += sb[i];
        out[0] = tot * (1.0f / BT);
    }
}

// ---------------------------------------------------------------------------
// Host entry
// ---------------------------------------------------------------------------
extern "C" void kernel_launch(void* const* d_in, const int* in_sizes, int n_in,
                              void* d_out, int out_size) {
    (void)in_sizes; (void)n_in;
    const float* idx     = (const float*)d_in[0];
    const int*   targets = (const int*)d_in[1];
    const float* W_emb   = (const float*)d_in[2];
    const float* W_attn  = (const float*)d_in[3];
    const float* W_out   = (const float*)d_in[4];
    float* out = (float*)d_out;

    float *x, *h, *qkv, *nll, *lscr, *wattn_r, *wout_r;
    int* tok;
    cudaGetSymbolAddress((void**)&x,       g_x);
    cudaGetSymbolAddress((void**)&h,       g_h);
    cudaGetSymbolAddress((void**)&qkv,     g_qkv);
    cudaGetSymbolAddress((void**)&nll,     g_nll);
    cudaGetSymbolAddress((void**)&lscr,    g_logits_scratch);
    cudaGetSymbolAddress((void**)&wattn_r, g_wattn_r);
    cudaGetSymbolAddress((void**)&wout_r,  g_wout_r);
    cudaGetSymbolAddress((void**)&tok,     g_tok);

    cudaFuncSetAttribute(attn_mma_kernel,
                         cudaFuncAttributeMaxDynamicSharedMemorySize, ATTN_SMEM);
    cudaFuncSetAttribute(gemm_tf32_cp_kernel,
                         cudaFuncAttributeMaxDynamicSharedMemorySize, G_SMEM);

    const size_t BTV = (size_t)BT * Vn;
    float* logits = ((size_t)out_size >= BTV) ? out : lscr;
    float* lossp  = ((size_t)out_size > BTV) ? (out + BTV)
                  : ((out_size == 1) ? out : nullptr);

    // weight prep (tf32 rna rounding, once per launch)
    round_tf32_kernel<<<2048, 256>>>((const float4*)W_attn, (float4*)wattn_r,
                                     (int)((size_t)Ln * D3 * Dn / 4));
    round_tf32_kernel<<<2048, 256>>>((const float4*)W_out, (float4*)wout_r,
                                     (int)((size_t)Vn * Dn / 4));

    tok_kernel<<<BT, 256>>>(idx, tok);
    embed_kernel<<<BT, 256>>>(W_emb, tok, x);

    for (int l = 0; l < Ln; l++) {
        ln_kernel<<<BT, 256>>>(x, h);
        gemm_tf32_cp_kernel<<<dim3(D3 / 128, BT / 128), 256, G_SMEM>>>(
            h, wattn_r + (size_t)l * D3 * Dn, qkv, D3);
        attn_mma_kernel<<<dim3(Tn / 128, Hn, Bsz), 256, ATTN_SMEM>>>(qkv, x);
    }

    ln_kernel<<<BT, 256>>>(x, h);
    gemm_tf32_cp_kernel<<<dim3(Vn / 128, BT / 128), 256, G_SMEM>>>(h, wout_r, logits, Vn);

    if (lossp) {
        nll_kernel<<<BT, 256>>>(logits, targets, nll);
        loss_kernel<<<1, 256>>>(nll, lossp);
    }
}

// round 6
// speedup vs baseline: 9.5271x; 1.8190x over previous
#include <cuda_runtime.h>
#include <cuda_fp16.h>
#include <cstdint>
#include <cstdio>

// Problem constants
#define Bsz 8
#define Tn  1024
#define Vn  8192
#define Dn  1024
#define Hn  16
#define Ln  6
#define HDn 64
#define BT  (Bsz*Tn)      // 8192 rows
#define D3  (3*Dn)        // 3072

// ---------------------------------------------------------------------------
// Scratch
// ---------------------------------------------------------------------------
__device__ float  g_x[(size_t)BT * Dn];
__device__ __half g_h[(size_t)BT * Dn];              // LN output (fp16)
__device__ float  g_qkv[(size_t)BT * D3];
__device__ float  g_logits_scratch[(size_t)BT * Vn];
__device__ __half g_wattn_h[(size_t)Ln * D3 * Dn];   // fp16 W_attn
__device__ __half g_wout_h[(size_t)Vn * Dn];         // fp16 W_out
__device__ int    g_tok[BT];
__device__ float  g_nll[BT];

// ---------------------------------------------------------------------------
// helpers
// ---------------------------------------------------------------------------
__device__ __forceinline__ uint32_t smem_u32(const void* p) {
    uint32_t a;
    asm("{ .reg .u64 t; cvta.to.shared.u64 t, %1; cvt.u32.u64 %0, t; }"
        : "=r"(a) : "l"(p));
    return a;
}
__device__ __forceinline__ void cp_async16(uint32_t dst, const void* src) {
    asm volatile("cp.async.cg.shared.global [%0], [%1], 16;" :: "r"(dst), "l"(src));
}
__device__ __forceinline__ void cp_commit() {
    asm volatile("cp.async.commit_group;" ::: "memory");
}
template <int N> __device__ __forceinline__ void cp_wait() {
    asm volatile("cp.async.wait_group %0;" :: "n"(N) : "memory");
}
__device__ __forceinline__ void ldm4(uint32_t* r, uint32_t addr) {
    asm volatile("ldmatrix.sync.aligned.m8n8.x4.shared.b16 {%0,%1,%2,%3}, [%4];"
                 : "=r"(r[0]), "=r"(r[1]), "=r"(r[2]), "=r"(r[3]) : "r"(addr));
}
__device__ __forceinline__ void mma_f16(float* c, const uint32_t* a,
                                        uint32_t b0, uint32_t b1) {
    asm volatile(
        "mma.sync.aligned.m16n8k16.row.col.f32.f16.f16.f32 "
        "{%0,%1,%2,%3}, {%4,%5,%6,%7}, {%8,%9}, {%0,%1,%2,%3};"
        : "+f"(c[0]), "+f"(c[1]), "+f"(c[2]), "+f"(c[3])
        : "r"(a[0]), "r"(a[1]), "r"(a[2]), "r"(a[3]), "r"(b0), "r"(b1));
}
// split (x,y) into fp16 hi + fp16 lo (hi+lo ~ exact to ~2^-22)
__device__ __forceinline__ void splith2(float x, float y, __half2& hi, __half2& lo) {
    hi = __floats2half2_rn(x, y);
    float2 b = __half22float2(hi);
    lo = __floats2half2_rn(x - b.x, y - b.y);
}

// ---------------------------------------------------------------------------
// 0. Convert fp32 weights to fp16 once per launch
// ---------------------------------------------------------------------------
__global__ void __launch_bounds__(256) f2h_kernel(const float2* __restrict__ in,
                                                  __half2* __restrict__ out, int n2) {
    for (int i = blockIdx.x * 256 + threadIdx.x; i < n2; i += gridDim.x * 256) {
        float2 v = in[i];
        out[i] = __floats2half2_rn(v.x, v.y);
    }
}

// ---------------------------------------------------------------------------
// 1. Token ids from one-hot
// ---------------------------------------------------------------------------
__global__ void __launch_bounds__(256) tok_kernel(const float* __restrict__ idx,
                                                  int* __restrict__ tok) {
    const int row = blockIdx.x;
    const float* r = idx + (size_t)row * Vn;
    for (int v = threadIdx.x; v < Vn; v += 256) {
        if (r[v] > 0.5f) tok[row] = v;
    }
}

// ---------------------------------------------------------------------------
// 2. Embedding gather
// ---------------------------------------------------------------------------
__global__ void __launch_bounds__(256) embed_kernel(const float* __restrict__ W_emb,
                                                    const int* __restrict__ tok,
                                                    float* __restrict__ x) {
    const int row = blockIdx.x;
    const int t = tok[row];
    float* xr = x + (size_t)row * Dn;
    for (int d = threadIdx.x; d < Dn; d += 256)
        xr[d] = W_emb[(size_t)d * Vn + t];
}

// ---------------------------------------------------------------------------
// 3. LayerNorm -> fp16 output (feeds fp16 GEMM A operand)
// ---------------------------------------------------------------------------
__global__ void __launch_bounds__(256) ln_kernel(const float* __restrict__ in,
                                                 __half* __restrict__ out) {
    const int row = blockIdx.x;
    const float* r = in + (size_t)row * Dn;
    float s = 0.f, ss = 0.f;
    for (int d = threadIdx.x; d < Dn; d += 256) {
        float v = r[d];
        s += v; ss += v * v;
    }
    #pragma unroll
    for (int o = 16; o > 0; o >>= 1) {
        s  += __shfl_xor_sync(0xffffffffu, s,  o);
        ss += __shfl_xor_sync(0xffffffffu, ss, o);
    }
    __shared__ float sb[8], qb[8];
    const int w = threadIdx.x >> 5, lane = threadIdx.x & 31;
    if (lane == 0) { sb[w] = s; qb[w] = ss; }
    __syncthreads();
    float ts = 0.f, tq = 0.f;
    #pragma unroll
    for (int i = 0; i < 8; i++) { ts += sb[i]; tq += qb[i]; }
    const float mu   = ts * (1.0f / Dn);
    const float var  = tq * (1.0f / Dn) - mu * mu;
    const float rstd = rsqrtf(var + 1e-5f);
    __half* o2 = out + (size_t)row * Dn;
    for (int d = threadIdx.x; d < Dn; d += 256)
        o2[d] = __float2half_rn((r[d] - mu) * rstd);
}

// ---------------------------------------------------------------------------
// 4. fp16 HMMA GEMM (cp.async 3-stage + ldmatrix):
//    C[M,N] = A[M,K]*B[N,K]^T; A,B fp16 row-major; tiles 128x128, BK=64, K=1024.
// ---------------------------------------------------------------------------
#define GS 3
#define G_HST 72
#define G_TILEH (128 * G_HST)
#define G_STAGEH (2 * G_TILEH)
#define G_SMEM (GS * G_STAGEH * 2)      // 110592 bytes
#define G_NCH (Dn / 64)                 // 16

__global__ void __launch_bounds__(256, 2) gemm_f16_kernel(
    const __half* __restrict__ A, const __half* __restrict__ Bm,
    float* __restrict__ C, int N) {
    extern __shared__ __half gsmh[];
    const uint32_t smb = smem_u32(gsmh);

    const int tid  = threadIdx.x;
    const int warp = tid >> 5, lane = tid & 31;
    const int wm = (warp >> 2) * 64;
    const int wn = (warp & 3) * 32;
    const int frow = lane >> 2;
    const int fcol = lane & 3;

    const __half* Ab = A  + (size_t)blockIdx.y * 128 * Dn;
    const __half* Bb = Bm + (size_t)blockIdx.x * 128 * Dn;

    // ldmatrix per-lane byte offsets (within a stage's A or B tile)
    const int lmat = lane >> 3, lmr = lane & 7;
    uint32_t a_off[4], b_off[2];
    #pragma unroll
    for (int mi = 0; mi < 4; mi++)
        a_off[mi] = (uint32_t)(((wm + mi * 16 + (lmat & 1) * 8 + lmr) * G_HST
                                + (lmat >> 1) * 8) * 2);
    #pragma unroll
    for (int np = 0; np < 2; np++)
        b_off[np] = (uint32_t)(((wn + np * 16 + (lmat >> 1) * 8 + lmr) * G_HST
                                + (lmat & 1) * 8) * 2);

    const int sr  = tid >> 3;            // staging row 0..31
    const int seg = tid & 7;             // 8-half segment

    auto load_chunk = [&](int chunk, int stage) {
        const uint32_t abase = smb + (uint32_t)(stage * G_STAGEH) * 2;
        const uint32_t bbase = abase + G_TILEH * 2;
        const size_t kof = (size_t)chunk * 64 + seg * 8;
        #pragma unroll
        for (int i = 0; i < 4; i++) {
            const int r = sr + i * 32;
            cp_async16(abase + (uint32_t)(r * G_HST + seg * 8) * 2,
                       Ab + (size_t)r * Dn + kof);
            cp_async16(bbase + (uint32_t)(r * G_HST + seg * 8) * 2,
                       Bb + (size_t)r * Dn + kof);
        }
    };

    float acc[4][4][4];
    #pragma unroll
    for (int i = 0; i < 4; i++)
        #pragma unroll
        for (int j = 0; j < 4; j++)
            #pragma unroll
            for (int v = 0; v < 4; v++) acc[i][j][v] = 0.f;

    load_chunk(0, 0); cp_commit();
    load_chunk(1, 1); cp_commit();

    for (int c = 0; c < G_NCH; c++) {
        if (c + 2 < G_NCH) { load_chunk(c + 2, (c + 2) % GS); cp_commit(); }
        const int rem = G_NCH - 1 - c;
        if (rem >= 2)      cp_wait<2>();
        else if (rem == 1) cp_wait<1>();
        else               cp_wait<0>();
        __syncthreads();

        const uint32_t abase = smb + (uint32_t)((c % GS) * G_STAGEH) * 2;
        const uint32_t bbase = abase + G_TILEH * 2;

        #pragma unroll
        for (int kc = 0; kc < 4; kc++) {
            const uint32_t kb = kc * 32;       // 16 halfs = 32 bytes
            uint32_t af[4][4], bf[2][4];
            #pragma unroll
            for (int mi = 0; mi < 4; mi++) ldm4(af[mi], abase + a_off[mi] + kb);
            #pragma unroll
            for (int np = 0; np < 2; np++) ldm4(bf[np], bbase + b_off[np] + kb);
            #pragma unroll
            for (int mi = 0; mi < 4; mi++) {
                #pragma unroll
                for (int nj = 0; nj < 4; nj++) {
                    const uint32_t* b = bf[nj >> 1];
                    if (nj & 1) mma_f16(acc[mi][nj], af[mi], b[2], b[3]);
                    else        mma_f16(acc[mi][nj], af[mi], b[0], b[1]);
                }
            }
        }
        __syncthreads();
    }

    #pragma unroll
    for (int mi = 0; mi < 4; mi++) {
        #pragma unroll
        for (int nj = 0; nj < 4; nj++) {
            const int row = blockIdx.y * 128 + wm + mi * 16 + frow;
            const int col = blockIdx.x * 128 + wn + nj * 8 + fcol * 2;
            *(float2*)(C + (size_t)row * N + col) =
                make_float2(acc[mi][nj][0], acc[mi][nj][1]);
            *(float2*)(C + (size_t)(row + 8) * N + col) =
                make_float2(acc[mi][nj][2], acc[mi][nj][3]);
        }
    }
}

// ---------------------------------------------------------------------------
// 5. Causal flash attention: split-fp16 (hi/lo) m16n8k16 mma, fp32-accurate.
//    Block 128 q-rows x head x batch; 8 warps x 16 q-rows; KV tiles of 64.
//    Smem (halfs, stride 72): Qhi/Qlo[128], Khi/Klo[64], Vthi/Vtlo[64] (transposed),
//    Phi/Plo[128]. V transpose staged via float Vf aliased on the P region.
// ---------------------------------------------------------------------------
#define AST 72
#define ATTN_SMEM ((2*128*AST + 2*64*AST + 2*64*AST + 2*128*AST) * 2)  // 110592

__global__ void __launch_bounds__(256, 2) attn_f16_kernel(
    const float* __restrict__ qkv, float* __restrict__ x) {
    extern __shared__ __half sm[];
    __half* Qhi = sm;
    __half* Qlo = Qhi + 128 * AST;
    __half* Khi = Qlo + 128 * AST;
    __half* Klo = Khi + 64 * AST;
    __half* Vthi = Klo + 64 * AST;
    __half* Vtlo = Vthi + 64 * AST;
    __half* Phi = Vtlo + 64 * AST;
    __half* Plo = Phi + 128 * AST;
    float*  Vf  = (float*)Phi;           // [64][68] staging, aliased on P

    const int qt = blockIdx.x;           // 0..7
    const int h  = blockIdx.y;
    const int b  = blockIdx.z;
    const int tid = threadIdx.x;
    const int w = tid >> 5, lane = tid & 31;
    const int gid = lane >> 2, tig = lane & 3;
    const size_t base3 = (size_t)b * Tn * D3;
    const int hoff = h * HDn;

    // ldmatrix per-lane byte offsets (stride AST halfs)
    const int lmat = lane >> 3, lmr = lane & 7;
    const uint32_t qp_off = (uint32_t)(((w * 16 + (lmat & 1) * 8 + lmr) * AST
                                        + (lmat >> 1) * 8) * 2);   // Q and P (A frags)
    uint32_t kv_off[4];
    #pragma unroll
    for (int np = 0; np < 4; np++)
        kv_off[np] = (uint32_t)(((np * 16 + (lmat >> 1) * 8 + lmr) * AST
                                 + (lmat & 1) * 8) * 2);           // K and Vt (B frags)

    const uint32_t qhiA = smem_u32(Qhi), qloA = smem_u32(Qlo);
    const uint32_t khiA = smem_u32(Khi), kloA = smem_u32(Klo);
    const uint32_t vhiA = smem_u32(Vthi), vloA = smem_u32(Vtlo);
    const uint32_t phiA = smem_u32(Phi), ploA = smem_u32(Plo);

    // load + split Q tile [128][64]
    #pragma unroll
    for (int it = 0; it < 8; it++) {
        const int i = tid + it * 256;
        const int r = i >> 4, c4 = (i & 15) << 2;
        float4 v = *(const float4*)&qkv[base3 + (size_t)(qt * 128 + r) * D3 + hoff + c4];
        __half2 h01, l01, h23, l23;
        splith2(v.x, v.y, h01, l01);
        splith2(v.z, v.w, h23, l23);
        ((__half2*)Qhi)[r * (AST / 2) + (c4 >> 1)]     = h01;
        ((__half2*)Qhi)[r * (AST / 2) + (c4 >> 1) + 1] = h23;
        ((__half2*)Qlo)[r * (AST / 2) + (c4 >> 1)]     = l01;
        ((__half2*)Qlo)[r * (AST / 2) + (c4 >> 1) + 1] = l23;
    }

    float m0 = -1e30f, m1 = -1e30f, l0 = 0.f, l1 = 0.f;
    float accO[8][4];
    #pragma unroll
    for (int nt = 0; nt < 8; nt++)
        #pragma unroll
        for (int v = 0; v < 4; v++) accO[nt][v] = 0.f;

    const int prow = w * 16 + gid;
    const int r0g = qt * 128 + prow;
    const int r1g = r0g + 8;
    const int jt_end = 2 * qt + 1;

    const int td = tid & 63;                 // transpose: own d-column
    const int tk = (tid >> 6) << 4;          // k segment base

    for (int jt = 0; jt <= jt_end; jt++) {
        __syncthreads();   // prior P/Vt fully consumed; Q visible (iter 0)
        // load K (split in-place) and V (float staging in Vf)
        #pragma unroll
        for (int it = 0; it < 4; it++) {
            const int i = tid + it * 256;
            const int r = i >> 4, c4 = (i & 15) << 2;
            const size_t g = base3 + (size_t)(jt * 64 + r) * D3 + hoff + c4;
            float4 k4 = *(const float4*)&qkv[g + Dn];
            float4 v4 = *(const float4*)&qkv[g + 2 * Dn];
            __half2 h01, l01, h23, l23;
            splith2(k4.x, k4.y, h01, l01);
            splith2(k4.z, k4.w, h23, l23);
            ((__half2*)Khi)[r * (AST / 2) + (c4 >> 1)]     = h01;
            ((__half2*)Khi)[r * (AST / 2) + (c4 >> 1) + 1] = h23;
            ((__half2*)Klo)[r * (AST / 2) + (c4 >> 1)]     = l01;
            ((__half2*)Klo)[r * (AST / 2) + (c4 >> 1) + 1] = l23;
            *(float4*)&Vf[r * 68 + c4] = v4;
        }
        __syncthreads();   // Vf + K visible

        // transpose V -> Vthi/Vtlo ([d][k], split). Conflict-free Vf reads.
        #pragma unroll
        for (int j = 0; j < 8; j++) {
            const int k0 = tk + 2 * j;
            const float v0 = Vf[k0 * 68 + td];
            const float v1 = Vf[(k0 + 1) * 68 + td];
            __half2 hi2, lo2;
            splith2(v0, v1, hi2, lo2);
            ((__half2*)Vthi)[td * (AST / 2) + (k0 >> 1)] = hi2;
            ((__half2*)Vtlo)[td * (AST / 2) + (k0 >> 1)] = lo2;
        }

        // --- S = Q K^T (split-fp16: hh + h.lo + lo.h) ---
        float accS[8][4];
        #pragma unroll
        for (int nt = 0; nt < 8; nt++)
            #pragma unroll
            for (int v = 0; v < 4; v++) accS[nt][v] = 0.f;

        #pragma unroll
        for (int kc = 0; kc < 4; kc++) {
            const uint32_t kb = kc * 32;
            uint32_t ah[4], al[4];
            ldm4(ah, qhiA + qp_off + kb);
            ldm4(al, qloA + qp_off + kb);
            #pragma unroll
            for (int np = 0; np < 4; np++) {
                uint32_t bh[4], bl[4];
                ldm4(bh, khiA + kv_off[np] + kb);
                ldm4(bl, kloA + kv_off[np] + kb);
                mma_f16(accS[2 * np],     ah, bh[0], bh[1]);
                mma_f16(accS[2 * np],     ah, bl[0], bl[1]);
                mma_f16(accS[2 * np],     al, bh[0], bh[1]);
                mma_f16(accS[2 * np + 1], ah, bh[2], bh[3]);
                mma_f16(accS[2 * np + 1], ah, bl[2], bl[3]);
                mma_f16(accS[2 * np + 1], al, bh[2], bh[3]);
            }
        }
        __syncthreads();   // Vf consumed (P region reusable); Vt visible

        // --- scale + causal mask ---
        const bool diag = (jt * 64 + 63 > qt * 128);
        #pragma unroll
        for (int nt = 0; nt < 8; nt++) {
            const int c0 = jt * 64 + nt * 8 + 2 * tig;
            accS[nt][0] *= 0.125f; accS[nt][1] *= 0.125f;
            accS[nt][2] *= 0.125f; accS[nt][3] *= 0.125f;
            if (diag) {
                if (c0     > r0g) accS[nt][0] = -1e30f;
                if (c0 + 1 > r0g) accS[nt][1] = -1e30f;
                if (c0     > r1g) accS[nt][2] = -1e30f;
                if (c0 + 1 > r1g) accS[nt][3] = -1e30f;
            }
        }

        // --- online softmax ---
        float tm0 = -1e30f, tm1 = -1e30f;
        #pragma unroll
        for (int nt = 0; nt < 8; nt++) {
            tm0 = fmaxf(tm0, fmaxf(accS[nt][0], accS[nt][1]));
            tm1 = fmaxf(tm1, fmaxf(accS[nt][2], accS[nt][3]));
        }
        tm0 = fmaxf(tm0, __shfl_xor_sync(0xffffffffu, tm0, 1));
        tm0 = fmaxf(tm0, __shfl_xor_sync(0xffffffffu, tm0, 2));
        tm1 = fmaxf(tm1, __shfl_xor_sync(0xffffffffu, tm1, 1));
        tm1 = fmaxf(tm1, __shfl_xor_sync(0xffffffffu, tm1, 2));
        const float nm0 = fmaxf(m0, tm0), nm1 = fmaxf(m1, tm1);
        const float corr0 = __expf(m0 - nm0), corr1 = __expf(m1 - nm1);
        m0 = nm0; m1 = nm1;
        float ts0 = 0.f, ts1 = 0.f;
        #pragma unroll
        for (int nt = 0; nt < 8; nt++) {
            accS[nt][0] = __expf(accS[nt][0] - nm0);
            accS[nt][1] = __expf(accS[nt][1] - nm0);
            accS[nt][2] = __expf(accS[nt][2] - nm1);
            accS[nt][3] = __expf(accS[nt][3] - nm1);
            ts0 += accS[nt][0] + accS[nt][1];
            ts1 += accS[nt][2] + accS[nt][3];
        }
        ts0 += __shfl_xor_sync(0xffffffffu, ts0, 1);
        ts0 += __shfl_xor_sync(0xffffffffu, ts0, 2);
        ts1 += __shfl_xor_sync(0xffffffffu, ts1, 1);
        ts1 += __shfl_xor_sync(0xffffffffu, ts1, 2);
        l0 = l0 * corr0 + ts0;
        l1 = l1 * corr1 + ts1;
        #pragma unroll
        for (int nt = 0; nt < 8; nt++) {
            accO[nt][0] *= corr0; accO[nt][1] *= corr0;
            accO[nt][2] *= corr1; accO[nt][3] *= corr1;
        }

        // --- write P (own rows), split fp16 ---
        #pragma unroll
        for (int nt = 0; nt < 8; nt++) {
            __half2 hi2, lo2;
            splith2(accS[nt][0], accS[nt][1], hi2, lo2);
            ((__half2*)Phi)[prow * (AST / 2) + nt * 4 + tig] = hi2;
            ((__half2*)Plo)[prow * (AST / 2) + nt * 4 + tig] = lo2;
            splith2(accS[nt][2], accS[nt][3], hi2, lo2);
            ((__half2*)Phi)[(prow + 8) * (AST / 2) + nt * 4 + tig] = hi2;
            ((__half2*)Plo)[(prow + 8) * (AST / 2) + nt * 4 + tig] = lo2;
        }
        __syncwarp();

        // --- O += P V (split-fp16) ---
        #pragma unroll
        for (int kc = 0; kc < 4; kc++) {
            const uint32_t kb = kc * 32;
            uint32_t ah[4], al[4];
            ldm4(ah, phiA + qp_off + kb);
            ldm4(al, ploA + qp_off + kb);
            #pragma unroll
            for (int np = 0; np < 4; np++) {
                uint32_t bh[4], bl[4];
                ldm4(bh, vhiA + kv_off[np] + kb);
                ldm4(bl, vloA + kv_off[np] + kb);
                mma_f16(accO[2 * np],     ah, bh[0], bh[1]);
                mma_f16(accO[2 * np],     ah, bl[0], bl[1]);
                mma_f16(accO[2 * np],     al, bh[0], bh[1]);
                mma_f16(accO[2 * np + 1], ah, bh[2], bh[3]);
                mma_f16(accO[2 * np + 1], ah, bl[2], bl[3]);
                mma_f16(accO[2 * np + 1], al, bh[2], bh[3]);
            }
        }
    }

    // --- epilogue: x += O / l ---
    const float inv0 = 1.0f / l0, inv1 = 1.0f / l1;
    #pragma unroll
    for (int nt = 0; nt < 8; nt++) {
        const int col = hoff + nt * 8 + 2 * tig;
        float* p0 = &x[((size_t)b * Tn + r0g) * Dn + col];
        p0[0] += accO[nt][0] * inv0;
        p0[1] += accO[nt][1] * inv0;
        float* p1 = &x[((size_t)b * Tn + r1g) * Dn + col];
        p1[0] += accO[nt][2] * inv1;
        p1[1] += accO[nt][3] * inv1;
    }
}

// ---------------------------------------------------------------------------
// 6. Per-row NLL
// ---------------------------------------------------------------------------
__global__ void __launch_bounds__(256) nll_kernel(const float* __restrict__ logits,
                                                  const int* __restrict__ targets,
                                                  float* __restrict__ nll) {
    const int row = blockIdx.x;
    const float* r = logits + (size_t)row * Vn;
    float mx = -3.0e38f;
    for (int v = threadIdx.x; v < Vn; v += 256) mx = fmaxf(mx, r[v]);
    #pragma unroll
    for (int o = 16; o > 0; o >>= 1) mx = fmaxf(mx, __shfl_xor_sync(0xffffffffu, mx, o));
    __shared__ float mb[8];
    __shared__ float sbuf[8];
    const int w = threadIdx.x >> 5, lane = threadIdx.x & 31;
    if (lane == 0) mb[w] = mx;
    __syncthreads();
    float gm = mb[0];
    #pragma unroll
    for (int i = 1; i < 8; i++) gm = fmaxf(gm, mb[i]);

    float se = 0.f;
    for (int v = threadIdx.x; v < Vn; v += 256) se += __expf(r[v] - gm);
    #pragma unroll
    for (int o = 16; o > 0; o >>= 1) se += __shfl_xor_sync(0xffffffffu, se, o);
    if (lane == 0) sbuf[w] = se;
    __syncthreads();
    if (threadIdx.x == 0) {
        float tot = 0.f;
        #pragma unroll
        for (int i = 0; i < 8; i++) tot += sbuf[i];
        nll[row] = gm + logf(tot) - r[targets[row]];
    }
}

// ---------------------------------------------------------------------------
// 7. Mean over row NLLs
// ---------------------------------------------------------------------------
__global__ void __launch_bounds__(256) loss_kernel(const float* __restrict__ nll,
                                                   float* __restrict__ out) {
    float s = 0.f;
    for (int i = threadIdx.x; i < BT; i += 256) s += nll[i];
    #pragma unroll
    for (int o = 16; o > 0; o >>= 1) s += __shfl_xor_sync(0xffffffffu, s, o);
    __shared__ float sb[8];
    const int w = threadIdx.x >> 5, lane = threadIdx.x & 31;
    if (lane == 0) sb[w] = s;
    __syncthreads();
    if (threadIdx.x == 0) {
        float tot = 0.f;
        #pragma unroll
        for (int i = 0; i < 8; i++) tot += sb[i];
        out[0] = tot * (1.0f / BT);
    }
}

// ---------------------------------------------------------------------------
// Host entry
// ---------------------------------------------------------------------------
extern "C" void kernel_launch(void* const* d_in, const int* in_sizes, int n_in,
                              void* d_out, int out_size) {
    (void)in_sizes; (void)n_in;
    const float* idx     = (const float*)d_in[0];
    const int*   targets = (const int*)d_in[1];
    const float* W_emb   = (const float*)d_in[2];
    const float* W_attn  = (const float*)d_in[3];
    const float* W_out   = (const float*)d_in[4];
    float* out = (float*)d_out;

    float *x, *qkv, *nll, *lscr;
    __half *h, *wattn_h, *wout_h;
    int* tok;
    cudaGetSymbolAddress((void**)&x,       g_x);
    cudaGetSymbolAddress((void**)&h,       g_h);
    cudaGetSymbolAddress((void**)&qkv,     g_qkv);
    cudaGetSymbolAddress((void**)&nll,     g_nll);
    cudaGetSymbolAddress((void**)&lscr,    g_logits_scratch);
    cudaGetSymbolAddress((void**)&wattn_h, g_wattn_h);
    cudaGetSymbolAddress((void**)&wout_h,  g_wout_h);
    cudaGetSymbolAddress((void**)&tok,     g_tok);

    cudaFuncSetAttribute(attn_f16_kernel,
                         cudaFuncAttributeMaxDynamicSharedMemorySize, ATTN_SMEM);
    cudaFuncSetAttribute(gemm_f16_kernel,
                         cudaFuncAttributeMaxDynamicSharedMemorySize, G_SMEM);

    const size_t BTV = (size_t)BT * Vn;
    float* logits = ((size_t)out_size >= BTV) ? out : lscr;
    float* lossp  = ((size_t)out_size > BTV) ? (out + BTV)
                  : ((out_size == 1) ? out : nullptr);

    // weight prep (fp16 conversion, once per launch)
    f2h_kernel<<<2048, 256>>>((const float2*)W_attn, (__half2*)wattn_h,
                              (int)((size_t)Ln * D3 * Dn / 2));
    f2h_kernel<<<2048, 256>>>((const float2*)W_out, (__half2*)wout_h,
                              (int)((size_t)Vn * Dn / 2));

    tok_kernel<<<BT, 256>>>(idx, tok);
    embed_kernel<<<BT, 256>>>(W_emb, tok, x);

    for (int l = 0; l < Ln; l++) {
        ln_kernel<<<BT, 256>>>(x, h);
        gemm_f16_kernel<<<dim3(D3 / 128, BT / 128), 256, G_SMEM>>>(
            h, wattn_h + (size_t)l * D3 * Dn, qkv, D3);
        attn_f16_kernel<<<dim3(Tn / 128, Hn, Bsz), 256, ATTN_SMEM>>>(qkv, x);
    }

    ln_kernel<<<BT, 256>>>(x, h);
    gemm_f16_kernel<<<dim3(Vn / 128, BT / 128), 256, G_SMEM>>>(h, wout_h, logits, Vn);

    if (lossp) {
        nll_kernel<<<BT, 256>>>(logits, targets, nll);
        loss_kernel<<<1, 256>>>(nll, lossp);
    }
}